// round 4
// baseline (speedup 1.0000x reference)
#include <cuda_runtime.h>

#define N_NODES 50000
#define E_EDGES 800000
#define TOT_E   (E_EDGES + N_NODES)   // 850000, incl. self-loops
#define HID     32
#define HEADS   4
#define F1      (HEADS * HID)          // 128
#define NEG_SLOPE 0.2f

// ---- scratch (device globals; no allocation allowed) ----
__device__ int   g_cnt[N_NODES];            // per-dst degree (incl. self-loop)
__device__ int   g_off[N_NODES];            // exclusive prefix (CSR row start)
__device__ int   g_cur[N_NODES];            // scatter cursors
__device__ int   g_csr[TOT_E];              // src ids grouped by dst
__device__ __align__(16) float g_h1[N_NODES * F1];
__device__ __align__(16) float g_as1[N_NODES * HEADS];
__device__ __align__(16) float g_ad1[N_NODES * HEADS];
__device__ __align__(16) float g_h2[N_NODES * HID];
__device__ float g_as2[N_NODES];
__device__ float g_ad2[N_NODES];

__device__ __forceinline__ float warp_sum_f(float v) {
#pragma unroll
    for (int o = 16; o; o >>= 1) v += __shfl_xor_sync(0xffffffffu, v, o);
    return v;
}
__device__ __forceinline__ float lrelu(float e) { return e > 0.f ? e : NEG_SLOPE * e; }
__device__ __forceinline__ float elu(float v)   { return v > 0.f ? v : __expf(v) - 1.f; }

// ============================================================================
// K1: h1 = x @ W1; attention scalars via a = x·(W1@attᵀ). Also zeros g_cnt
// (runs before kH). 128 threads, 32 nodes per block.
// ============================================================================
__global__ void k1_node1(const float* __restrict__ x,  const float* __restrict__ W1,
                         const float* __restrict__ as1, const float* __restrict__ ad1) {
    __shared__ float sW[5 * F1];
    __shared__ float sva[5 * HEADS], svb[5 * HEADS];   // folded attention weights
    int t = threadIdx.x;
    int n0 = blockIdx.x * 32;
    if (t < 32 && n0 + t < N_NODES) g_cnt[n0 + t] = 0;     // fold kZ in

    for (int i = t; i < 5 * F1; i += 128) sW[i] = W1[i];
    if (t < 5 * HEADS) {
        int k = t / HEADS, h = t % HEADS;
        float s = 0.f, d = 0.f;
        for (int c = 0; c < HID; c++) {
            float w = W1[k * F1 + h * HID + c];
            s = fmaf(w, as1[h * HID + c], s);
            d = fmaf(w, ad1[h * HID + c], d);
        }
        sva[t] = s; svb[t] = d;
    }
    __syncthreads();

    for (int j = 0; j < 32; j++) {
        int n = n0 + j;
        if (n >= N_NODES) return;
        float xv[5];
#pragma unroll
        for (int k = 0; k < 5; k++) xv[k] = x[n * 5 + k];
        float h = 0.f;
#pragma unroll
        for (int k = 0; k < 5; k++) h = fmaf(xv[k], sW[k * F1 + t], h);
        g_h1[n * F1 + t] = h;
        if (t < HEADS) {
            float s = 0.f, d = 0.f;
#pragma unroll
            for (int k = 0; k < 5; k++) {
                s = fmaf(xv[k], sva[k * HEADS + t], s);
                d = fmaf(xv[k], svb[k * HEADS + t], d);
            }
            g_as1[n * HEADS + t] = s;
            g_ad1[n * HEADS + t] = d;
        }
    }
}

// ============================================================================
// kH: histogram degrees by dst (int atomics)
// ============================================================================
__global__ void kH(const int* __restrict__ ei) {
    int e = blockIdx.x * blockDim.x + threadIdx.x;
    if (e >= TOT_E) return;
    int dst = (e < E_EDGES) ? ei[E_EDGES + e] : (e - E_EDGES);
    atomicAdd(&g_cnt[dst], 1);
}

// ============================================================================
// kScan: single-block exclusive scan of g_cnt -> g_off/g_cur.
// 1024 threads; two passes over contiguous per-thread chunks (49 elems each).
// ============================================================================
#define SCAN_T 1024
#define SCAN_ITEMS ((N_NODES + SCAN_T - 1) / SCAN_T)   // 49
__global__ void kScan() {
    __shared__ int warp_tot[SCAN_T / 32];
    int t = threadIdx.x, lane = t & 31, wid = t >> 5;
    int base = t * SCAN_ITEMS;

    int sum = 0;
    for (int i = 0; i < SCAN_ITEMS; i++) {
        int idx = base + i;
        if (idx < N_NODES) sum += g_cnt[idx];
    }
    // block exclusive scan of per-thread sums
    int x = sum;
#pragma unroll
    for (int o = 1; o < 32; o <<= 1) {          // inclusive warp scan (all lanes)
        int y = __shfl_up_sync(0xffffffffu, x, o);
        if (lane >= o) x += y;
    }
    if (lane == 31) warp_tot[wid] = x;
    __syncthreads();
    if (wid == 0) {                             // full warp scans 32 warp totals
        int y = warp_tot[lane];
#pragma unroll
        for (int o = 1; o < 32; o <<= 1) {
            int z = __shfl_up_sync(0xffffffffu, y, o);
            if (lane >= o) y += z;
        }
        warp_tot[lane] = y;
    }
    __syncthreads();
    int run = x - sum + (wid ? warp_tot[wid - 1] : 0);   // thread's exclusive prefix

    for (int i = 0; i < SCAN_ITEMS; i++) {
        int idx = base + i;
        if (idx < N_NODES) {
            g_off[idx] = run;
            g_cur[idx] = run;
            run += g_cnt[idx];
        }
    }
}

// ============================================================================
// kC: scatter src ids grouped by dst
// ============================================================================
__global__ void kC(const int* __restrict__ ei) {
    int e = blockIdx.x * blockDim.x + threadIdx.x;
    if (e >= TOT_E) return;
    int src, dst;
    if (e < E_EDGES) { src = ei[e]; dst = ei[E_EDGES + e]; }
    else             { src = dst = e - E_EDGES; }
    int p = atomicAdd(&g_cur[dst], 1);
    g_csr[p] = src;
}

// ============================================================================
// kG12: FUSED layer-1 gather + layer-2 dense transform.
//   per dst node (one warp): softmax-aggregate h1[src] (reg accum, no atomics),
//   normalize + b1 + ELU -> smem row -> h2 = row @ W2 -> as2/ad2 scalars.
// Grid-stride over nodes so W2 (16KB smem) loads once per block.
// ============================================================================
__global__ void kG12(const float* __restrict__ b1, const float* __restrict__ W2,
                     const float* __restrict__ as2v, const float* __restrict__ ad2v) {
    __shared__ float sW2[F1 * HID];     // 16 KB
    __shared__ float sH[8][F1];         // 4 KB
    __shared__ float sAs2[HID], sAd2[HID];
    int t = threadIdx.x;
    for (int i = t; i < F1 * HID; i += 256) sW2[i] = W2[i];
    if (t < HID) { sAs2[t] = as2v[t]; sAd2[t] = ad2v[t]; }
    __syncthreads();

    int wid = t >> 5, lane = t & 31, head = lane >> 3;
    int f = lane * 4;
    float4 bv = *reinterpret_cast<const float4*>(&b1[f]);

    for (int n = blockIdx.x * 8 + wid; n < N_NODES; n += gridDim.x * 8) {
        float adv = g_ad1[n * HEADS + head];
        int beg = g_off[n], cnt = g_cnt[n];

        float a0 = 0.f, a1 = 0.f, a2 = 0.f, a3 = 0.f, den = 0.f;
        int src = g_csr[beg];
        for (int j = 0; j < cnt; j++) {
            int nsrc = (j + 1 < cnt) ? g_csr[beg + j + 1] : 0;
            float as = g_as1[src * HEADS + head];
            float w  = __expf(lrelu(as + adv));
            float4 hv = *reinterpret_cast<const float4*>(&g_h1[src * F1 + f]);
            a0 = fmaf(w, hv.x, a0);
            a1 = fmaf(w, hv.y, a1);
            a2 = fmaf(w, hv.z, a2);
            a3 = fmaf(w, hv.w, a3);
            den += w;
            src = nsrc;
        }
        float inv = 1.f / den;
        sH[wid][f + 0] = elu(fmaf(a0, inv, bv.x));
        sH[wid][f + 1] = elu(fmaf(a1, inv, bv.y));
        sH[wid][f + 2] = elu(fmaf(a2, inv, bv.z));
        sH[wid][f + 3] = elu(fmaf(a3, inv, bv.w));
        __syncwarp();

        float acc = 0.f;
#pragma unroll 8
        for (int k = 0; k < F1; k++) acc = fmaf(sH[wid][k], sW2[k * HID + lane], acc);
        g_h2[n * HID + lane] = acc;

        float ps = warp_sum_f(acc * sAs2[lane]);
        float pd = warp_sum_f(acc * sAd2[lane]);
        if (lane == 0) { g_as2[n] = ps; g_ad2[n] = pd; }
        __syncwarp();
    }
}

// ============================================================================
// kG2: layer-2 gather (1 head, 32 feats) + fused MLP head. One warp per node.
// ============================================================================
__global__ void kG2(const float* __restrict__ b2,  const float* __restrict__ Wc1,
                    const float* __restrict__ bc1, const float* __restrict__ Wc2,
                    const float* __restrict__ bc2, float* __restrict__ out) {
    __shared__ float sv[8][HID];
    int n = (blockIdx.x * blockDim.x + threadIdx.x) >> 5;
    if (n >= N_NODES) return;
    int lane = threadIdx.x & 31;
    int wid = (threadIdx.x >> 5) & 7;

    float adv = g_ad2[n];
    int beg = g_off[n], cnt = g_cnt[n];

    float acc = 0.f, den = 0.f;
    int src = g_csr[beg];
    for (int j = 0; j < cnt; j++) {
        int nsrc = (j + 1 < cnt) ? g_csr[beg + j + 1] : 0;
        float w = __expf(lrelu(g_as2[src] + adv));
        float h = g_h2[src * HID + lane];
        acc = fmaf(w, h, acc);
        den += w;
        src = nsrc;
    }
    float v = elu(acc / den + b2[lane]);
    sv[wid][lane] = v;
    __syncwarp();

    float tj = 0.f;
    if (lane < 16) {
        tj = bc1[lane];
#pragma unroll
        for (int c = 0; c < HID; c++) tj = fmaf(sv[wid][c], Wc1[c * 16 + lane], tj);
        tj = fmaxf(tj, 0.f) * Wc2[lane];
    }
#pragma unroll
    for (int o = 16; o; o >>= 1) tj += __shfl_xor_sync(0xffffffffu, tj, o);  // all lanes
    if (lane == 0) out[n] = tj + bc2[0];
}

// ============================================================================
extern "C" void kernel_launch(void* const* d_in, const int* in_sizes, int n_in,
                              void* d_out, int out_size) {
    const float* x   = (const float*)d_in[0];
    const int*   ei  = (const int*)  d_in[1];
    const float* W1  = (const float*)d_in[2];
    const float* as1 = (const float*)d_in[3];
    const float* ad1 = (const float*)d_in[4];
    const float* b1  = (const float*)d_in[5];
    const float* W2  = (const float*)d_in[6];
    const float* as2 = (const float*)d_in[7];
    const float* ad2 = (const float*)d_in[8];
    const float* b2  = (const float*)d_in[9];
    const float* Wc1 = (const float*)d_in[10];
    const float* bc1 = (const float*)d_in[11];
    const float* Wc2 = (const float*)d_in[12];
    const float* bc2 = (const float*)d_in[13];
    float* out = (float*)d_out;

    k1_node1<<<(N_NODES + 31) / 32, 128>>>(x, W1, as1, ad1);   // also zeros g_cnt
    kH   <<<(TOT_E + 255) / 256, 256>>>(ei);
    kScan<<<1, SCAN_T>>>();
    kC   <<<(TOT_E + 255) / 256, 256>>>(ei);
    kG12 <<<1184, 256>>>(b1, W2, as2, ad2);                     // 8 blocks/SM resident
    kG2  <<<(N_NODES * 32 + 255) / 256, 256>>>(b2, Wc1, bc1, Wc2, bc2, out);
}

// round 6
// speedup vs baseline: 1.0075x; 1.0075x over previous
#include <cuda_runtime.h>

#define N_NODES 50000
#define E_EDGES 800000
#define TOT_E   (E_EDGES + N_NODES)   // 850000, incl. self-loops
#define HID     32
#define HEADS   4
#define F1      (HEADS * HID)          // 128
#define NEG_SLOPE 0.2f

// ---- scratch (device globals; no allocation allowed) ----
__device__ int   g_cnt[N_NODES];            // per-dst degree (incl. self-loop)
__device__ int   g_off[N_NODES];            // exclusive prefix (CSR row start)
__device__ int   g_cur[N_NODES];            // scatter cursors
__device__ int   g_csr[TOT_E];              // src ids grouped by dst
__device__ __align__(16) float g_h1[N_NODES * F1];
__device__ __align__(16) float g_as1[N_NODES * HEADS];
__device__ __align__(16) float g_ad1[N_NODES * HEADS];
__device__ __align__(16) float g_out1[N_NODES * F1];   // post-softmax, post-ELU
__device__ __align__(16) float g_h2[N_NODES * HID];
__device__ float g_as2[N_NODES];
__device__ float g_ad2[N_NODES];

__device__ __forceinline__ float warp_sum_f(float v) {
#pragma unroll
    for (int o = 16; o; o >>= 1) v += __shfl_xor_sync(0xffffffffu, v, o);
    return v;
}
__device__ __forceinline__ float lrelu(float e) { return e > 0.f ? e : NEG_SLOPE * e; }
__device__ __forceinline__ float elu(float v)   { return v > 0.f ? v : __expf(v) - 1.f; }

// ============================================================================
// K1: h1 = x @ W1; attention scalars via a = x·(W1@attᵀ). Also zeros g_cnt.
// 128 threads, 32 nodes per block.
// ============================================================================
__global__ void k1_node1(const float* __restrict__ x,  const float* __restrict__ W1,
                         const float* __restrict__ as1, const float* __restrict__ ad1) {
    __shared__ float sW[5 * F1];
    __shared__ float sva[5 * HEADS], svb[5 * HEADS];
    int t = threadIdx.x;
    int n0 = blockIdx.x * 32;
    if (t < 32 && n0 + t < N_NODES) g_cnt[n0 + t] = 0;     // fold kZ in

    for (int i = t; i < 5 * F1; i += 128) sW[i] = W1[i];
    if (t < 5 * HEADS) {
        int k = t / HEADS, h = t % HEADS;
        float s = 0.f, d = 0.f;
        for (int c = 0; c < HID; c++) {
            float w = W1[k * F1 + h * HID + c];
            s = fmaf(w, as1[h * HID + c], s);
            d = fmaf(w, ad1[h * HID + c], d);
        }
        sva[t] = s; svb[t] = d;
    }
    __syncthreads();

    for (int j = 0; j < 32; j++) {
        int n = n0 + j;
        if (n >= N_NODES) return;
        float xv[5];
#pragma unroll
        for (int k = 0; k < 5; k++) xv[k] = x[n * 5 + k];
        float h = 0.f;
#pragma unroll
        for (int k = 0; k < 5; k++) h = fmaf(xv[k], sW[k * F1 + t], h);
        g_h1[n * F1 + t] = h;
        if (t < HEADS) {
            float s = 0.f, d = 0.f;
#pragma unroll
            for (int k = 0; k < 5; k++) {
                s = fmaf(xv[k], sva[k * HEADS + t], s);
                d = fmaf(xv[k], svb[k * HEADS + t], d);
            }
            g_as1[n * HEADS + t] = s;
            g_ad1[n * HEADS + t] = d;
        }
    }
}

// ============================================================================
// kH: histogram degrees by dst (int atomics)
// ============================================================================
__global__ void kH(const int* __restrict__ ei) {
    int e = blockIdx.x * blockDim.x + threadIdx.x;
    if (e >= TOT_E) return;
    int dst = (e < E_EDGES) ? ei[E_EDGES + e] : (e - E_EDGES);
    atomicAdd(&g_cnt[dst], 1);
}

// ============================================================================
// kScan: single-block exclusive scan of g_cnt -> g_off/g_cur (1024 threads)
// ============================================================================
#define SCAN_T 1024
#define SCAN_ITEMS ((N_NODES + SCAN_T - 1) / SCAN_T)   // 49
__global__ void kScan() {
    __shared__ int warp_tot[SCAN_T / 32];
    int t = threadIdx.x, lane = t & 31, wid = t >> 5;
    int base = t * SCAN_ITEMS;

    int sum = 0;
    for (int i = 0; i < SCAN_ITEMS; i++) {
        int idx = base + i;
        if (idx < N_NODES) sum += g_cnt[idx];
    }
    int x = sum;
#pragma unroll
    for (int o = 1; o < 32; o <<= 1) {
        int y = __shfl_up_sync(0xffffffffu, x, o);
        if (lane >= o) x += y;
    }
    if (lane == 31) warp_tot[wid] = x;
    __syncthreads();
    if (wid == 0) {
        int y = warp_tot[lane];
#pragma unroll
        for (int o = 1; o < 32; o <<= 1) {
            int z = __shfl_up_sync(0xffffffffu, y, o);
            if (lane >= o) y += z;
        }
        warp_tot[lane] = y;
    }
    __syncthreads();
    int run = x - sum + (wid ? warp_tot[wid - 1] : 0);

    for (int i = 0; i < SCAN_ITEMS; i++) {
        int idx = base + i;
        if (idx < N_NODES) {
            g_off[idx] = run;
            g_cur[idx] = run;
            run += g_cnt[idx];
        }
    }
}

// ============================================================================
// kC: scatter src ids grouped by dst
// ============================================================================
__global__ void kC(const int* __restrict__ ei) {
    int e = blockIdx.x * blockDim.x + threadIdx.x;
    if (e >= TOT_E) return;
    int src, dst;
    if (e < E_EDGES) { src = ei[e]; dst = ei[E_EDGES + e]; }
    else             { src = dst = e - E_EDGES; }
    int p = atomicAdd(&g_cur[dst], 1);
    g_csr[p] = src;
}

// ============================================================================
// KG1: layer-1 gather. One warp per dst node (50000 warps — full TLP).
// 2-wide unrolled edge loop: two independent csr->(as1,h1) chains in flight.
// ============================================================================
__global__ void kG1(const float* __restrict__ b1) {
    int n = (blockIdx.x * blockDim.x + threadIdx.x) >> 5;
    if (n >= N_NODES) return;
    int lane = threadIdx.x & 31;
    int head = lane >> 3;
    int f = lane * 4;

    float adv = g_ad1[n * HEADS + head];
    int beg = g_off[n], cnt = g_cnt[n];

    float a0 = 0.f, a1 = 0.f, a2 = 0.f, a3 = 0.f, den = 0.f;
    int j = 0;
    for (; j + 1 < cnt; j += 2) {
        int s0 = g_csr[beg + j];
        int s1 = g_csr[beg + j + 1];
        float e0 = g_as1[s0 * HEADS + head];
        float e1 = g_as1[s1 * HEADS + head];
        float4 h0 = *reinterpret_cast<const float4*>(&g_h1[s0 * F1 + f]);
        float4 h1 = *reinterpret_cast<const float4*>(&g_h1[s1 * F1 + f]);
        float w0 = __expf(lrelu(e0 + adv));
        float w1 = __expf(lrelu(e1 + adv));
        a0 = fmaf(w0, h0.x, a0); a1 = fmaf(w0, h0.y, a1);
        a2 = fmaf(w0, h0.z, a2); a3 = fmaf(w0, h0.w, a3);
        a0 = fmaf(w1, h1.x, a0); a1 = fmaf(w1, h1.y, a1);
        a2 = fmaf(w1, h1.z, a2); a3 = fmaf(w1, h1.w, a3);
        den += w0 + w1;
    }
    if (j < cnt) {
        int s0 = g_csr[beg + j];
        float e0 = g_as1[s0 * HEADS + head];
        float4 h0 = *reinterpret_cast<const float4*>(&g_h1[s0 * F1 + f]);
        float w0 = __expf(lrelu(e0 + adv));
        a0 = fmaf(w0, h0.x, a0); a1 = fmaf(w0, h0.y, a1);
        a2 = fmaf(w0, h0.z, a2); a3 = fmaf(w0, h0.w, a3);
        den += w0;
    }
    float inv = 1.f / den;
    float4 bv = *reinterpret_cast<const float4*>(&b1[f]);
    float4 o;
    o.x = elu(fmaf(a0, inv, bv.x));
    o.y = elu(fmaf(a1, inv, bv.y));
    o.z = elu(fmaf(a2, inv, bv.z));
    o.w = elu(fmaf(a3, inv, bv.w));
    *reinterpret_cast<float4*>(&g_out1[n * F1 + f]) = o;
}

// ============================================================================
// K3: h2 = out1 @ W2 + attention scalars. 8 nodes/block, W2 in smem.
// ============================================================================
__global__ void k3_node2(const float* __restrict__ W2,
                         const float* __restrict__ as2, const float* __restrict__ ad2) {
    __shared__ float sW2[F1 * HID];
    __shared__ float sH[8][F1];
    int t = threadIdx.x;
    for (int i = t; i < F1 * HID; i += 256) sW2[i] = W2[i];
    __syncthreads();

    int wid = t >> 5, lane = t & 31;
    int n = blockIdx.x * 8 + wid;
    if (n >= N_NODES) return;

    float4 hv = *reinterpret_cast<const float4*>(&g_out1[n * F1 + lane * 4]);
    sH[wid][lane * 4 + 0] = hv.x;
    sH[wid][lane * 4 + 1] = hv.y;
    sH[wid][lane * 4 + 2] = hv.z;
    sH[wid][lane * 4 + 3] = hv.w;
    __syncwarp();

    float acc = 0.f;
#pragma unroll 8
    for (int k = 0; k < F1; k++) acc = fmaf(sH[wid][k], sW2[k * HID + lane], acc);
    g_h2[n * HID + lane] = acc;

    float ps = warp_sum_f(acc * as2[lane]);
    float pd = warp_sum_f(acc * ad2[lane]);
    if (lane == 0) { g_as2[n] = ps; g_ad2[n] = pd; }
}

// ============================================================================
// KG2: layer-2 gather + fused MLP head. One warp per node; 2-wide unroll.
// ============================================================================
__global__ void kG2(const float* __restrict__ b2,  const float* __restrict__ Wc1,
                    const float* __restrict__ bc1, const float* __restrict__ Wc2,
                    const float* __restrict__ bc2, float* __restrict__ out) {
    __shared__ float sv[8][HID];
    int n = (blockIdx.x * blockDim.x + threadIdx.x) >> 5;
    if (n >= N_NODES) return;
    int lane = threadIdx.x & 31;
    int wid = (threadIdx.x >> 5) & 7;

    float adv = g_ad2[n];
    int beg = g_off[n], cnt = g_cnt[n];

    float acc = 0.f, den = 0.f;
    int j = 0;
    for (; j + 1 < cnt; j += 2) {
        int s0 = g_csr[beg + j];
        int s1 = g_csr[beg + j + 1];
        float e0 = g_as2[s0];
        float e1 = g_as2[s1];
        float h0 = g_h2[s0 * HID + lane];
        float h1 = g_h2[s1 * HID + lane];
        float w0 = __expf(lrelu(e0 + adv));
        float w1 = __expf(lrelu(e1 + adv));
        acc = fmaf(w0, h0, acc);
        acc = fmaf(w1, h1, acc);
        den += w0 + w1;
    }
    if (j < cnt) {
        int s0 = g_csr[beg + j];
        float w0 = __expf(lrelu(g_as2[s0] + adv));
        acc = fmaf(w0, g_h2[s0 * HID + lane], acc);
        den += w0;
    }
    float v = elu(acc / den + b2[lane]);
    sv[wid][lane] = v;
    __syncwarp();

    float tj = 0.f;
    if (lane < 16) {
        tj = bc1[lane];
#pragma unroll
        for (int c = 0; c < HID; c++) tj = fmaf(sv[wid][c], Wc1[c * 16 + lane], tj);
        tj = fmaxf(tj, 0.f) * Wc2[lane];
    }
#pragma unroll
    for (int o = 16; o; o >>= 1) tj += __shfl_xor_sync(0xffffffffu, tj, o);  // all lanes
    if (lane == 0) out[n] = tj + bc2[0];
}

// ============================================================================
extern "C" void kernel_launch(void* const* d_in, const int* in_sizes, int n_in,
                              void* d_out, int out_size) {
    const float* x   = (const float*)d_in[0];
    const int*   ei  = (const int*)  d_in[1];
    const float* W1  = (const float*)d_in[2];
    const float* as1 = (const float*)d_in[3];
    const float* ad1 = (const float*)d_in[4];
    const float* b1  = (const float*)d_in[5];
    const float* W2  = (const float*)d_in[6];
    const float* as2 = (const float*)d_in[7];
    const float* ad2 = (const float*)d_in[8];
    const float* b2  = (const float*)d_in[9];
    const float* Wc1 = (const float*)d_in[10];
    const float* bc1 = (const float*)d_in[11];
    const float* Wc2 = (const float*)d_in[12];
    const float* bc2 = (const float*)d_in[13];
    float* out = (float*)d_out;

    k1_node1<<<(N_NODES + 31) / 32, 128>>>(x, W1, as1, ad1);   // also zeros g_cnt
    kH   <<<(TOT_E + 255) / 256, 256>>>(ei);
    kScan<<<1, SCAN_T>>>();
    kC   <<<(TOT_E + 255) / 256, 256>>>(ei);
    kG1  <<<(N_NODES * 32 + 255) / 256, 256>>>(b1);            // 1 warp/node, full TLP
    k3_node2<<<(N_NODES + 7) / 8, 256>>>(W2, as2, ad2);
    kG2  <<<(N_NODES * 32 + 255) / 256, 256>>>(b2, Wc1, bc1, Wc2, bc2, out);
}

// round 7
// speedup vs baseline: 1.4513x; 1.4405x over previous
#include <cuda_runtime.h>

#define N_NODES 50000
#define E_EDGES 800000
#define TOT_E   (E_EDGES + N_NODES)   // 850000, incl. self-loops
#define HID     32
#define HEADS   4
#define F1      (HEADS * HID)          // 128
#define NEG_SLOPE 0.2f

#define SCAN_CHUNK 512
#define NB_SCAN    ((N_NODES + SCAN_CHUNK - 1) / SCAN_CHUNK)   // 98

// ---- scratch (device globals; no allocation allowed) ----
__device__ int   g_cnt[N_NODES];            // per-dst degree (incl. self-loop)
__device__ int   g_off[N_NODES];            // exclusive prefix (CSR row start)
__device__ int   g_cur[N_NODES];            // scatter cursors
__device__ int   g_bsum[NB_SCAN];           // scan partials
__device__ int   g_boff[NB_SCAN];
__device__ int   g_csr[TOT_E];              // src ids grouped by dst
__device__ __align__(16) float g_h1[N_NODES * F1];
__device__ __align__(16) float g_as1[N_NODES * HEADS];
__device__ __align__(16) float g_ad1[N_NODES * HEADS];
__device__ __align__(16) float g_out1[N_NODES * F1];   // post-softmax, post-ELU
__device__ __align__(16) float g_h2[N_NODES * HID];
__device__ float g_as2[N_NODES];
__device__ float g_ad2[N_NODES];

__device__ __forceinline__ float warp_sum_f(float v) {
#pragma unroll
    for (int o = 16; o; o >>= 1) v += __shfl_xor_sync(0xffffffffu, v, o);
    return v;
}
__device__ __forceinline__ int warp_sum_i(int v) {
#pragma unroll
    for (int o = 16; o; o >>= 1) v += __shfl_xor_sync(0xffffffffu, v, o);
    return v;
}
__device__ __forceinline__ float lrelu(float e) { return e > 0.f ? e : NEG_SLOPE * e; }
__device__ __forceinline__ float elu(float v)   { return v > 0.f ? v : __expf(v) - 1.f; }

// ============================================================================
// K1: h1 = x @ W1; attention scalars via a = x·(W1@attᵀ). Also zeros g_cnt.
// 128 threads, 32 nodes per block.
// ============================================================================
__global__ void k1_node1(const float* __restrict__ x,  const float* __restrict__ W1,
                         const float* __restrict__ as1, const float* __restrict__ ad1) {
    __shared__ float sW[5 * F1];
    __shared__ float sva[5 * HEADS], svb[5 * HEADS];
    int t = threadIdx.x;
    int n0 = blockIdx.x * 32;
    if (t < 32 && n0 + t < N_NODES) g_cnt[n0 + t] = 0;     // fold kZ in

    for (int i = t; i < 5 * F1; i += 128) sW[i] = W1[i];
    if (t < 5 * HEADS) {
        int k = t / HEADS, h = t % HEADS;
        float s = 0.f, d = 0.f;
        for (int c = 0; c < HID; c++) {
            float w = W1[k * F1 + h * HID + c];
            s = fmaf(w, as1[h * HID + c], s);
            d = fmaf(w, ad1[h * HID + c], d);
        }
        sva[t] = s; svb[t] = d;
    }
    __syncthreads();

    for (int j = 0; j < 32; j++) {
        int n = n0 + j;
        if (n >= N_NODES) return;
        float xv[5];
#pragma unroll
        for (int k = 0; k < 5; k++) xv[k] = x[n * 5 + k];
        float h = 0.f;
#pragma unroll
        for (int k = 0; k < 5; k++) h = fmaf(xv[k], sW[k * F1 + t], h);
        g_h1[n * F1 + t] = h;
        if (t < HEADS) {
            float s = 0.f, d = 0.f;
#pragma unroll
            for (int k = 0; k < 5; k++) {
                s = fmaf(xv[k], sva[k * HEADS + t], s);
                d = fmaf(xv[k], svb[k * HEADS + t], d);
            }
            g_as1[n * HEADS + t] = s;
            g_ad1[n * HEADS + t] = d;
        }
    }
}

// ============================================================================
// kH: histogram degrees by dst (int atomics)
// ============================================================================
__global__ void kH(const int* __restrict__ ei) {
    int e = blockIdx.x * blockDim.x + threadIdx.x;
    if (e >= TOT_E) return;
    int dst = (e < E_EDGES) ? ei[E_EDGES + e] : (e - E_EDGES);
    atomicAdd(&g_cnt[dst], 1);
}

// ============================================================================
// Multi-block COALESCED scan (R3 form; the R4/R6 single-block version was the
// 60us regression: contiguous per-thread chunks = 32-way uncoalesced on 1 SM)
// ============================================================================
__global__ void kS1() {                             // per-chunk sums (coalesced)
    __shared__ int ws[SCAN_CHUNK / 32];
    int t = threadIdx.x, b = blockIdx.x;
    int i = b * SCAN_CHUNK + t;
    int x = (i < N_NODES) ? g_cnt[i] : 0;
    x = warp_sum_i(x);
    if ((t & 31) == 0) ws[t >> 5] = x;
    __syncthreads();
    if (t == 0) {
        int tot = 0;
#pragma unroll
        for (int w = 0; w < SCAN_CHUNK / 32; w++) tot += ws[w];
        g_bsum[b] = tot;
    }
}

__global__ void kS2() {                             // scan 98 partials via smem
    __shared__ int sv[NB_SCAN];
    int t = threadIdx.x;                            // 128 threads
    if (t < NB_SCAN) sv[t] = g_bsum[t];             // one coalesced load wave
    __syncthreads();
    if (t == 0) {                                   // serial scan in smem (fast)
        int run = 0;
        for (int b = 0; b < NB_SCAN; b++) { int v = sv[b]; sv[b] = run; run += v; }
    }
    __syncthreads();
    if (t < NB_SCAN) g_boff[t] = sv[t];             // one coalesced store wave
}

__global__ void kS3() {                             // chunk-local scan + base (coalesced)
    __shared__ int ws[SCAN_CHUNK / 32 + 1];
    int t = threadIdx.x, b = blockIdx.x;
    int i = b * SCAN_CHUNK + t;
    int lane = t & 31, wid = t >> 5;
    int v = (i < N_NODES) ? g_cnt[i] : 0;
    int x = v;
#pragma unroll
    for (int o = 1; o < 32; o <<= 1) {              // inclusive warp scan (all lanes)
        int y = __shfl_up_sync(0xffffffffu, x, o);
        if (lane >= o) x += y;
    }
    if (lane == 31) ws[wid + 1] = x;
    __syncthreads();
    if (t == 0) {
        ws[0] = 0;
        for (int w = 1; w < SCAN_CHUNK / 32; w++) ws[w] += ws[w - 1];
    }
    __syncthreads();
    int excl = x - v + ws[wid] + g_boff[b];
    if (i < N_NODES) { g_off[i] = excl; g_cur[i] = excl; }
}

// ============================================================================
// kC: scatter src ids grouped by dst
// ============================================================================
__global__ void kC(const int* __restrict__ ei) {
    int e = blockIdx.x * blockDim.x + threadIdx.x;
    if (e >= TOT_E) return;
    int src, dst;
    if (e < E_EDGES) { src = ei[e]; dst = ei[E_EDGES + e]; }
    else             { src = dst = e - E_EDGES; }
    int p = atomicAdd(&g_cur[dst], 1);
    g_csr[p] = src;
}

// ============================================================================
// KG1: layer-1 gather. One warp per dst node (50000 warps — full TLP).
// 2-wide unrolled edge loop: two independent csr->(as1,h1) chains in flight.
// ============================================================================
__global__ void kG1(const float* __restrict__ b1) {
    int n = (blockIdx.x * blockDim.x + threadIdx.x) >> 5;
    if (n >= N_NODES) return;
    int lane = threadIdx.x & 31;
    int head = lane >> 3;
    int f = lane * 4;

    float adv = g_ad1[n * HEADS + head];
    int beg = g_off[n], cnt = g_cnt[n];

    float a0 = 0.f, a1 = 0.f, a2 = 0.f, a3 = 0.f, den = 0.f;
    int j = 0;
    for (; j + 1 < cnt; j += 2) {
        int s0 = g_csr[beg + j];
        int s1 = g_csr[beg + j + 1];
        float e0 = g_as1[s0 * HEADS + head];
        float e1 = g_as1[s1 * HEADS + head];
        float4 h0 = *reinterpret_cast<const float4*>(&g_h1[s0 * F1 + f]);
        float4 h1 = *reinterpret_cast<const float4*>(&g_h1[s1 * F1 + f]);
        float w0 = __expf(lrelu(e0 + adv));
        float w1 = __expf(lrelu(e1 + adv));
        a0 = fmaf(w0, h0.x, a0); a1 = fmaf(w0, h0.y, a1);
        a2 = fmaf(w0, h0.z, a2); a3 = fmaf(w0, h0.w, a3);
        a0 = fmaf(w1, h1.x, a0); a1 = fmaf(w1, h1.y, a1);
        a2 = fmaf(w1, h1.z, a2); a3 = fmaf(w1, h1.w, a3);
        den += w0 + w1;
    }
    if (j < cnt) {
        int s0 = g_csr[beg + j];
        float e0 = g_as1[s0 * HEADS + head];
        float4 h0 = *reinterpret_cast<const float4*>(&g_h1[s0 * F1 + f]);
        float w0 = __expf(lrelu(e0 + adv));
        a0 = fmaf(w0, h0.x, a0); a1 = fmaf(w0, h0.y, a1);
        a2 = fmaf(w0, h0.z, a2); a3 = fmaf(w0, h0.w, a3);
        den += w0;
    }
    float inv = 1.f / den;
    float4 bv = *reinterpret_cast<const float4*>(&b1[f]);
    float4 o;
    o.x = elu(fmaf(a0, inv, bv.x));
    o.y = elu(fmaf(a1, inv, bv.y));
    o.z = elu(fmaf(a2, inv, bv.z));
    o.w = elu(fmaf(a3, inv, bv.w));
    *reinterpret_cast<float4*>(&g_out1[n * F1 + f]) = o;
}

// ============================================================================
// K3: h2 = out1 @ W2 + attention scalars. 8 nodes/block, W2 in smem.
// ============================================================================
__global__ void k3_node2(const float* __restrict__ W2,
                         const float* __restrict__ as2, const float* __restrict__ ad2) {
    __shared__ float sW2[F1 * HID];
    __shared__ float sH[8][F1];
    int t = threadIdx.x;
    for (int i = t; i < F1 * HID; i += 256) sW2[i] = W2[i];
    __syncthreads();

    int wid = t >> 5, lane = t & 31;
    int n = blockIdx.x * 8 + wid;
    if (n >= N_NODES) return;

    float4 hv = *reinterpret_cast<const float4*>(&g_out1[n * F1 + lane * 4]);
    sH[wid][lane * 4 + 0] = hv.x;
    sH[wid][lane * 4 + 1] = hv.y;
    sH[wid][lane * 4 + 2] = hv.z;
    sH[wid][lane * 4 + 3] = hv.w;
    __syncwarp();

    float acc = 0.f;
#pragma unroll 8
    for (int k = 0; k < F1; k++) acc = fmaf(sH[wid][k], sW2[k * HID + lane], acc);
    g_h2[n * HID + lane] = acc;

    float ps = warp_sum_f(acc * as2[lane]);
    float pd = warp_sum_f(acc * ad2[lane]);
    if (lane == 0) { g_as2[n] = ps; g_ad2[n] = pd; }
}

// ============================================================================
// KG2: layer-2 gather + fused MLP head. One warp per node; 2-wide unroll.
// ============================================================================
__global__ void kG2(const float* __restrict__ b2,  const float* __restrict__ Wc1,
                    const float* __restrict__ bc1, const float* __restrict__ Wc2,
                    const float* __restrict__ bc2, float* __restrict__ out) {
    __shared__ float sv[8][HID];
    int n = (blockIdx.x * blockDim.x + threadIdx.x) >> 5;
    if (n >= N_NODES) return;
    int lane = threadIdx.x & 31;
    int wid = (threadIdx.x >> 5) & 7;

    float adv = g_ad2[n];
    int beg = g_off[n], cnt = g_cnt[n];

    float acc = 0.f, den = 0.f;
    int j = 0;
    for (; j + 1 < cnt; j += 2) {
        int s0 = g_csr[beg + j];
        int s1 = g_csr[beg + j + 1];
        float e0 = g_as2[s0];
        float e1 = g_as2[s1];
        float h0 = g_h2[s0 * HID + lane];
        float h1 = g_h2[s1 * HID + lane];
        float w0 = __expf(lrelu(e0 + adv));
        float w1 = __expf(lrelu(e1 + adv));
        acc = fmaf(w0, h0, acc);
        acc = fmaf(w1, h1, acc);
        den += w0 + w1;
    }
    if (j < cnt) {
        int s0 = g_csr[beg + j];
        float w0 = __expf(lrelu(g_as2[s0] + adv));
        acc = fmaf(w0, g_h2[s0 * HID + lane], acc);
        den += w0;
    }
    float v = elu(acc / den + b2[lane]);
    sv[wid][lane] = v;
    __syncwarp();

    float tj = 0.f;
    if (lane < 16) {
        tj = bc1[lane];
#pragma unroll
        for (int c = 0; c < HID; c++) tj = fmaf(sv[wid][c], Wc1[c * 16 + lane], tj);
        tj = fmaxf(tj, 0.f) * Wc2[lane];
    }
#pragma unroll
    for (int o = 16; o; o >>= 1) tj += __shfl_xor_sync(0xffffffffu, tj, o);  // all lanes
    if (lane == 0) out[n] = tj + bc2[0];
}

// ============================================================================
extern "C" void kernel_launch(void* const* d_in, const int* in_sizes, int n_in,
                              void* d_out, int out_size) {
    const float* x   = (const float*)d_in[0];
    const int*   ei  = (const int*)  d_in[1];
    const float* W1  = (const float*)d_in[2];
    const float* as1 = (const float*)d_in[3];
    const float* ad1 = (const float*)d_in[4];
    const float* b1  = (const float*)d_in[5];
    const float* W2  = (const float*)d_in[6];
    const float* as2 = (const float*)d_in[7];
    const float* ad2 = (const float*)d_in[8];
    const float* b2  = (const float*)d_in[9];
    const float* Wc1 = (const float*)d_in[10];
    const float* bc1 = (const float*)d_in[11];
    const float* Wc2 = (const float*)d_in[12];
    const float* bc2 = (const float*)d_in[13];
    float* out = (float*)d_out;

    k1_node1<<<(N_NODES + 31) / 32, 128>>>(x, W1, as1, ad1);   // also zeros g_cnt
    kH <<<(TOT_E + 255) / 256, 256>>>(ei);
    kS1<<<NB_SCAN, SCAN_CHUNK>>>();
    kS2<<<1, 128>>>();
    kS3<<<NB_SCAN, SCAN_CHUNK>>>();
    kC <<<(TOT_E + 255) / 256, 256>>>(ei);
    kG1<<<(N_NODES * 32 + 255) / 256, 256>>>(b1);              // 1 warp/node, full TLP
    k3_node2<<<(N_NODES + 7) / 8, 256>>>(W2, as2, ad2);
    kG2<<<(N_NODES * 32 + 255) / 256, 256>>>(b2, Wc1, bc1, Wc2, bc2, out);
}

// round 8
// speedup vs baseline: 1.4984x; 1.0325x over previous
#include <cuda_runtime.h>
#include <cuda_fp16.h>

#define N_NODES 50000
#define E_EDGES 800000
#define TOT_E   (E_EDGES + N_NODES)   // 850000, incl. self-loops
#define HID     32
#define HEADS   4
#define F1      (HEADS * HID)          // 128
#define NEG_SLOPE 0.2f

#define SCAN_CHUNK 512
#define NB_SCAN    ((N_NODES + SCAN_CHUNK - 1) / SCAN_CHUNK)   // 98

// ---- scratch (device globals; no allocation allowed) ----
__device__ int   g_cnt[N_NODES];            // per-dst degree (incl. self-loop)
__device__ int   g_off[N_NODES];            // exclusive prefix (CSR row start)
__device__ int   g_cur[N_NODES];            // scatter cursors
__device__ int   g_bsum[NB_SCAN];           // scan partials
__device__ int   g_csr[TOT_E];              // src ids grouped by dst
__device__ __align__(16) __half g_h1h[N_NODES * F1];   // layer1 feats, fp16 (12.8MB)
__device__ __align__(16) float  g_as1[N_NODES * HEADS];
__device__ __align__(16) float  g_ad1[N_NODES * HEADS];
__device__ __align__(16) float  g_out1[N_NODES * F1];  // post-softmax, post-ELU
__device__ __align__(16) __half g_h2h[N_NODES * HID];  // layer2 feats, fp16 (3.2MB)
__device__ float g_as2[N_NODES];
__device__ float g_ad2[N_NODES];

__device__ __forceinline__ float warp_sum_f(float v) {
#pragma unroll
    for (int o = 16; o; o >>= 1) v += __shfl_xor_sync(0xffffffffu, v, o);
    return v;
}
__device__ __forceinline__ int warp_sum_i(int v) {
#pragma unroll
    for (int o = 16; o; o >>= 1) v += __shfl_xor_sync(0xffffffffu, v, o);
    return v;
}
__device__ __forceinline__ float lrelu(float e) { return e > 0.f ? e : NEG_SLOPE * e; }
__device__ __forceinline__ float elu(float v)   { return v > 0.f ? v : __expf(v) - 1.f; }

// ============================================================================
// K1: h1 = x @ W1 (stored fp16); attention scalars via a = x·(W1@attᵀ).
// Also zeros g_cnt. 128 threads, 32 nodes per block.
// ============================================================================
__global__ void k1_node1(const float* __restrict__ x,  const float* __restrict__ W1,
                         const float* __restrict__ as1, const float* __restrict__ ad1) {
    __shared__ float sW[5 * F1];
    __shared__ float sva[5 * HEADS], svb[5 * HEADS];
    int t = threadIdx.x;
    int n0 = blockIdx.x * 32;
    if (t < 32 && n0 + t < N_NODES) g_cnt[n0 + t] = 0;     // fold kZ in

    for (int i = t; i < 5 * F1; i += 128) sW[i] = W1[i];
    if (t < 5 * HEADS) {
        int k = t / HEADS, h = t % HEADS;
        float s = 0.f, d = 0.f;
        for (int c = 0; c < HID; c++) {
            float w = W1[k * F1 + h * HID + c];
            s = fmaf(w, as1[h * HID + c], s);
            d = fmaf(w, ad1[h * HID + c], d);
        }
        sva[t] = s; svb[t] = d;
    }
    __syncthreads();

    for (int j = 0; j < 32; j++) {
        int n = n0 + j;
        if (n >= N_NODES) return;
        float xv[5];
#pragma unroll
        for (int k = 0; k < 5; k++) xv[k] = x[n * 5 + k];
        float h = 0.f;
#pragma unroll
        for (int k = 0; k < 5; k++) h = fmaf(xv[k], sW[k * F1 + t], h);
        g_h1h[n * F1 + t] = __float2half_rn(h);
        if (t < HEADS) {
            float s = 0.f, d = 0.f;
#pragma unroll
            for (int k = 0; k < 5; k++) {
                s = fmaf(xv[k], sva[k * HEADS + t], s);
                d = fmaf(xv[k], svb[k * HEADS + t], d);
            }
            g_as1[n * HEADS + t] = s;
            g_ad1[n * HEADS + t] = d;
        }
    }
}

// ============================================================================
// kH: histogram degrees by dst (int atomics)
// ============================================================================
__global__ void kH(const int* __restrict__ ei) {
    int e = blockIdx.x * blockDim.x + threadIdx.x;
    if (e >= TOT_E) return;
    int dst = (e < E_EDGES) ? ei[E_EDGES + e] : (e - E_EDGES);
    atomicAdd(&g_cnt[dst], 1);
}

// ============================================================================
// Coalesced 2-kernel scan: kS1 per-chunk sums; kS3 local scan + inline base
// (each block sums the <=98 partials itself — kills the kS2 launch).
// ============================================================================
__global__ void kS1() {
    __shared__ int ws[SCAN_CHUNK / 32];
    int t = threadIdx.x, b = blockIdx.x;
    int i = b * SCAN_CHUNK + t;
    int x = (i < N_NODES) ? g_cnt[i] : 0;
    x = warp_sum_i(x);
    if ((t & 31) == 0) ws[t >> 5] = x;
    __syncthreads();
    if (t == 0) {
        int tot = 0;
#pragma unroll
        for (int w = 0; w < SCAN_CHUNK / 32; w++) tot += ws[w];
        g_bsum[b] = tot;
    }
}

__global__ void kS3() {
    __shared__ int ws[SCAN_CHUNK / 32 + 1];
    __shared__ int sbs[NB_SCAN];
    __shared__ int sbase;
    int t = threadIdx.x, b = blockIdx.x;
    int i = b * SCAN_CHUNK + t;
    int lane = t & 31, wid = t >> 5;

    if (t < NB_SCAN) sbs[t] = g_bsum[t];            // coalesced load of partials

    int v = (i < N_NODES) ? g_cnt[i] : 0;
    int x = v;
#pragma unroll
    for (int o = 1; o < 32; o <<= 1) {              // inclusive warp scan (all lanes)
        int y = __shfl_up_sync(0xffffffffu, x, o);
        if (lane >= o) x += y;
    }
    if (lane == 31) ws[wid + 1] = x;
    __syncthreads();
    if (t == 0) {
        ws[0] = 0;
        for (int w = 1; w < SCAN_CHUNK / 32; w++) ws[w] += ws[w - 1];
        int base = 0;
        for (int q = 0; q < b; q++) base += sbs[q];  // inline boff (serial, smem)
        sbase = base;
    }
    __syncthreads();
    int excl = x - v + ws[wid] + sbase;
    if (i < N_NODES) { g_off[i] = excl; g_cur[i] = excl; }
}

// ============================================================================
// kC: scatter src ids grouped by dst
// ============================================================================
__global__ void kC(const int* __restrict__ ei) {
    int e = blockIdx.x * blockDim.x + threadIdx.x;
    if (e >= TOT_E) return;
    int src, dst;
    if (e < E_EDGES) { src = ei[e]; dst = ei[E_EDGES + e]; }
    else             { src = dst = e - E_EDGES; }
    int p = atomicAdd(&g_cur[dst], 1);
    g_csr[p] = src;
}

// ============================================================================
// KG1: layer-1 gather over fp16 feats. One warp per dst node; 2-wide unroll.
// Each lane owns 4 features = 8B per edge (half of the fp32 version's 16B).
// ============================================================================
__global__ void kG1(const float* __restrict__ b1) {
    int n = (blockIdx.x * blockDim.x + threadIdx.x) >> 5;
    if (n >= N_NODES) return;
    int lane = threadIdx.x & 31;
    int head = lane >> 3;
    int f = lane * 4;

    float adv = g_ad1[n * HEADS + head];
    int beg = g_off[n], cnt = g_cnt[n];

    float a0 = 0.f, a1 = 0.f, a2 = 0.f, a3 = 0.f, den = 0.f;
    int j = 0;
    for (; j + 1 < cnt; j += 2) {
        int s0 = g_csr[beg + j];
        int s1 = g_csr[beg + j + 1];
        float e0 = g_as1[s0 * HEADS + head];
        float e1 = g_as1[s1 * HEADS + head];
        uint2 r0 = *reinterpret_cast<const uint2*>(&g_h1h[s0 * F1 + f]);
        uint2 r1 = *reinterpret_cast<const uint2*>(&g_h1h[s1 * F1 + f]);
        float w0 = __expf(lrelu(e0 + adv));
        float w1 = __expf(lrelu(e1 + adv));
        float2 p00 = __half22float2(*reinterpret_cast<__half2*>(&r0.x));
        float2 p01 = __half22float2(*reinterpret_cast<__half2*>(&r0.y));
        float2 p10 = __half22float2(*reinterpret_cast<__half2*>(&r1.x));
        float2 p11 = __half22float2(*reinterpret_cast<__half2*>(&r1.y));
        a0 = fmaf(w0, p00.x, a0); a1 = fmaf(w0, p00.y, a1);
        a2 = fmaf(w0, p01.x, a2); a3 = fmaf(w0, p01.y, a3);
        a0 = fmaf(w1, p10.x, a0); a1 = fmaf(w1, p10.y, a1);
        a2 = fmaf(w1, p11.x, a2); a3 = fmaf(w1, p11.y, a3);
        den += w0 + w1;
    }
    if (j < cnt) {
        int s0 = g_csr[beg + j];
        float e0 = g_as1[s0 * HEADS + head];
        uint2 r0 = *reinterpret_cast<const uint2*>(&g_h1h[s0 * F1 + f]);
        float w0 = __expf(lrelu(e0 + adv));
        float2 p00 = __half22float2(*reinterpret_cast<__half2*>(&r0.x));
        float2 p01 = __half22float2(*reinterpret_cast<__half2*>(&r0.y));
        a0 = fmaf(w0, p00.x, a0); a1 = fmaf(w0, p00.y, a1);
        a2 = fmaf(w0, p01.x, a2); a3 = fmaf(w0, p01.y, a3);
        den += w0;
    }
    float inv = 1.f / den;
    float4 bv = *reinterpret_cast<const float4*>(&b1[f]);
    float4 o;
    o.x = elu(fmaf(a0, inv, bv.x));
    o.y = elu(fmaf(a1, inv, bv.y));
    o.z = elu(fmaf(a2, inv, bv.z));
    o.w = elu(fmaf(a3, inv, bv.w));
    *reinterpret_cast<float4*>(&g_out1[n * F1 + f]) = o;
}

// ============================================================================
// K3: h2 = out1 @ W2 (stored fp16) + attention scalars. 8 nodes/block.
// ============================================================================
__global__ void k3_node2(const float* __restrict__ W2,
                         const float* __restrict__ as2, const float* __restrict__ ad2) {
    __shared__ float sW2[F1 * HID];
    __shared__ float sH[8][F1];
    int t = threadIdx.x;
    for (int i = t; i < F1 * HID; i += 256) sW2[i] = W2[i];
    __syncthreads();

    int wid = t >> 5, lane = t & 31;
    int n = blockIdx.x * 8 + wid;
    if (n >= N_NODES) return;

    float4 hv = *reinterpret_cast<const float4*>(&g_out1[n * F1 + lane * 4]);
    sH[wid][lane * 4 + 0] = hv.x;
    sH[wid][lane * 4 + 1] = hv.y;
    sH[wid][lane * 4 + 2] = hv.z;
    sH[wid][lane * 4 + 3] = hv.w;
    __syncwarp();

    float acc = 0.f;
#pragma unroll 8
    for (int k = 0; k < F1; k++) acc = fmaf(sH[wid][k], sW2[k * HID + lane], acc);
    g_h2h[n * HID + lane] = __float2half_rn(acc);

    float ps = warp_sum_f(acc * as2[lane]);
    float pd = warp_sum_f(acc * ad2[lane]);
    if (lane == 0) { g_as2[n] = ps; g_ad2[n] = pd; }
}

// ============================================================================
// KG2: layer-2 gather (fp16 feats) + fused MLP head. One warp per node.
// ============================================================================
__global__ void kG2(const float* __restrict__ b2,  const float* __restrict__ Wc1,
                    const float* __restrict__ bc1, const float* __restrict__ Wc2,
                    const float* __restrict__ bc2, float* __restrict__ out) {
    __shared__ float sv[8][HID];
    int n = (blockIdx.x * blockDim.x + threadIdx.x) >> 5;
    if (n >= N_NODES) return;
    int lane = threadIdx.x & 31;
    int wid = (threadIdx.x >> 5) & 7;

    float adv = g_ad2[n];
    int beg = g_off[n], cnt = g_cnt[n];

    float acc = 0.f, den = 0.f;
    int j = 0;
    for (; j + 1 < cnt; j += 2) {
        int s0 = g_csr[beg + j];
        int s1 = g_csr[beg + j + 1];
        float e0 = g_as2[s0];
        float e1 = g_as2[s1];
        float h0 = __half2float(g_h2h[s0 * HID + lane]);
        float h1 = __half2float(g_h2h[s1 * HID + lane]);
        float w0 = __expf(lrelu(e0 + adv));
        float w1 = __expf(lrelu(e1 + adv));
        acc = fmaf(w0, h0, acc);
        acc = fmaf(w1, h1, acc);
        den += w0 + w1;
    }
    if (j < cnt) {
        int s0 = g_csr[beg + j];
        float w0 = __expf(lrelu(g_as2[s0] + adv));
        acc = fmaf(w0, __half2float(g_h2h[s0 * HID + lane]), acc);
        den += w0;
    }
    float v = elu(acc / den + b2[lane]);
    sv[wid][lane] = v;
    __syncwarp();

    float tj = 0.f;
    if (lane < 16) {
        tj = bc1[lane];
#pragma unroll
        for (int c = 0; c < HID; c++) tj = fmaf(sv[wid][c], Wc1[c * 16 + lane], tj);
        tj = fmaxf(tj, 0.f) * Wc2[lane];
    }
#pragma unroll
    for (int o = 16; o; o >>= 1) tj += __shfl_xor_sync(0xffffffffu, tj, o);  // all lanes
    if (lane == 0) out[n] = tj + bc2[0];
}

// ============================================================================
extern "C" void kernel_launch(void* const* d_in, const int* in_sizes, int n_in,
                              void* d_out, int out_size) {
    const float* x   = (const float*)d_in[0];
    const int*   ei  = (const int*)  d_in[1];
    const float* W1  = (const float*)d_in[2];
    const float* as1 = (const float*)d_in[3];
    const float* ad1 = (const float*)d_in[4];
    const float* b1  = (const float*)d_in[5];
    const float* W2  = (const float*)d_in[6];
    const float* as2 = (const float*)d_in[7];
    const float* ad2 = (const float*)d_in[8];
    const float* b2  = (const float*)d_in[9];
    const float* Wc1 = (const float*)d_in[10];
    const float* bc1 = (const float*)d_in[11];
    const float* Wc2 = (const float*)d_in[12];
    const float* bc2 = (const float*)d_in[13];
    float* out = (float*)d_out;

    k1_node1<<<(N_NODES + 31) / 32, 128>>>(x, W1, as1, ad1);   // also zeros g_cnt
    kH <<<(TOT_E + 255) / 256, 256>>>(ei);
    kS1<<<NB_SCAN, SCAN_CHUNK>>>();
    kS3<<<NB_SCAN, SCAN_CHUNK>>>();                            // inline base (no kS2)
    kC <<<(TOT_E + 255) / 256, 256>>>(ei);
    kG1<<<(N_NODES * 32 + 255) / 256, 256>>>(b1);              // 1 warp/node, full TLP
    k3_node2<<<(N_NODES + 7) / 8, 256>>>(W2, as2, ad2);
    kG2<<<(N_NODES * 32 + 255) / 256, 256>>>(b2, Wc1, bc1, Wc2, bc2, out);
}

// round 10
// speedup vs baseline: 1.6924x; 1.1295x over previous
#include <cuda_runtime.h>
#include <cuda_fp16.h>

#define N_NODES 50000
#define E_EDGES 800000
#define TOT_E   (E_EDGES + N_NODES)   // 850000, incl. self-loops
#define HID     32
#define HEADS   4
#define F1      (HEADS * HID)          // 128
#define NEG_SLOPE 0.2f

#define SCAN_CHUNK 512
#define NB_SCAN    ((N_NODES + SCAN_CHUNK - 1) / SCAN_CHUNK)   // 98

// ---- scratch (device globals; no allocation allowed) ----
__device__ int   g_cnt[N_NODES];
__device__ int   g_off[N_NODES];
__device__ int   g_cur[N_NODES];
__device__ int   g_bsum[NB_SCAN];
__device__ int   g_csr[TOT_E];
__device__ __align__(16) __half g_h1h[N_NODES * F1];   // layer1 feats fp16 (12.8MB)
__device__ __align__(16) float  g_as1[N_NODES * HEADS];
__device__ __align__(16) float  g_ad1[N_NODES * HEADS];
__device__ __align__(16) float  g_out1[N_NODES * F1];  // post-softmax, post-ELU
__device__ __align__(16) float  g_h2[N_NODES * HID];   // layer2 feats fp32
__device__ float g_as2[N_NODES];
__device__ float g_ad2[N_NODES];

__device__ __forceinline__ float warp_sum_f(float v) {
#pragma unroll
    for (int o = 16; o; o >>= 1) v += __shfl_xor_sync(0xffffffffu, v, o);
    return v;
}
__device__ __forceinline__ int warp_sum_i(int v) {
#pragma unroll
    for (int o = 16; o; o >>= 1) v += __shfl_xor_sync(0xffffffffu, v, o);
    return v;
}
__device__ __forceinline__ float lrelu(float e) { return e > 0.f ? e : NEG_SLOPE * e; }
__device__ __forceinline__ float elu(float v)   { return v > 0.f ? v : __expf(v) - 1.f; }

// ============================================================================
// K1: h1 = x @ W1 (stored fp16); attention scalars via a = x·(W1@attᵀ).
// Also zeros g_cnt. 128 threads, 32 nodes per block.
// ============================================================================
__global__ void k1_node1(const float* __restrict__ x,  const float* __restrict__ W1,
                         const float* __restrict__ as1, const float* __restrict__ ad1) {
    __shared__ float sW[5 * F1];
    __shared__ float sva[5 * HEADS], svb[5 * HEADS];
    int t = threadIdx.x;
    int n0 = blockIdx.x * 32;
    if (t < 32 && n0 + t < N_NODES) g_cnt[n0 + t] = 0;

    for (int i = t; i < 5 * F1; i += 128) sW[i] = W1[i];
    if (t < 5 * HEADS) {
        int k = t / HEADS, h = t % HEADS;
        float s = 0.f, d = 0.f;
        for (int c = 0; c < HID; c++) {
            float w = W1[k * F1 + h * HID + c];
            s = fmaf(w, as1[h * HID + c], s);
            d = fmaf(w, ad1[h * HID + c], d);
        }
        sva[t] = s; svb[t] = d;
    }
    __syncthreads();

    for (int j = 0; j < 32; j++) {
        int n = n0 + j;
        if (n >= N_NODES) return;
        float xv[5];
#pragma unroll
        for (int k = 0; k < 5; k++) xv[k] = x[n * 5 + k];
        float h = 0.f;
#pragma unroll
        for (int k = 0; k < 5; k++) h = fmaf(xv[k], sW[k * F1 + t], h);
        g_h1h[n * F1 + t] = __float2half_rn(h);
        if (t < HEADS) {
            float s = 0.f, d = 0.f;
#pragma unroll
            for (int k = 0; k < 5; k++) {
                s = fmaf(xv[k], sva[k * HEADS + t], s);
                d = fmaf(xv[k], svb[k * HEADS + t], d);
            }
            g_as1[n * HEADS + t] = s;
            g_ad1[n * HEADS + t] = d;
        }
    }
}

// ============================================================================
// kH: histogram by dst — 4 striped edges/thread, 4 independent REDs in flight.
// FIX vs R9: threads with gid >= KH_T must exit, else boundary edges are
// processed twice (once at i=0 by gid, once at i=1 by gid-KH_T).
// ============================================================================
#define EB 4
#define KH_T ((TOT_E + EB - 1) / EB)   // 212500 stripe width
__global__ void kH(const int* __restrict__ ei) {
    int gid = blockIdx.x * blockDim.x + threadIdx.x;
    if (gid >= KH_T) return;                       // <-- the fix
#pragma unroll
    for (int i = 0; i < EB; i++) {
        int e = gid + i * KH_T;
        if (e < TOT_E) {
            int dst = (e < E_EDGES) ? ei[E_EDGES + e] : (e - E_EDGES);
            atomicAdd(&g_cnt[dst], 1);
        }
    }
}

// ============================================================================
// Coalesced 2-kernel scan (kS2 inlined into kS3)
// ============================================================================
__global__ void kS1() {
    __shared__ int ws[SCAN_CHUNK / 32];
    int t = threadIdx.x, b = blockIdx.x;
    int i = b * SCAN_CHUNK + t;
    int x = (i < N_NODES) ? g_cnt[i] : 0;
    x = warp_sum_i(x);
    if ((t & 31) == 0) ws[t >> 5] = x;
    __syncthreads();
    if (t == 0) {
        int tot = 0;
#pragma unroll
        for (int w = 0; w < SCAN_CHUNK / 32; w++) tot += ws[w];
        g_bsum[b] = tot;
    }
}

__global__ void kS3() {
    __shared__ int ws[SCAN_CHUNK / 32 + 1];
    __shared__ int sbs[NB_SCAN];
    __shared__ int sbase;
    int t = threadIdx.x, b = blockIdx.x;
    int i = b * SCAN_CHUNK + t;
    int lane = t & 31, wid = t >> 5;

    if (t < NB_SCAN) sbs[t] = g_bsum[t];

    int v = (i < N_NODES) ? g_cnt[i] : 0;
    int x = v;
#pragma unroll
    for (int o = 1; o < 32; o <<= 1) {
        int y = __shfl_up_sync(0xffffffffu, x, o);
        if (lane >= o) x += y;
    }
    if (lane == 31) ws[wid + 1] = x;
    __syncthreads();
    if (t == 0) {
        ws[0] = 0;
        for (int w = 1; w < SCAN_CHUNK / 32; w++) ws[w] += ws[w - 1];
        int base = 0;
        for (int q = 0; q < b; q++) base += sbs[q];
        sbase = base;
    }
    __syncthreads();
    int excl = x - v + ws[wid] + sbase;
    if (i < N_NODES) { g_off[i] = excl; g_cur[i] = excl; }
}

// ============================================================================
// kC: scatter src by dst — 4 striped edges/thread (same stripe guard fix)
// ============================================================================
__global__ void kC(const int* __restrict__ ei) {
    int gid = blockIdx.x * blockDim.x + threadIdx.x;
    if (gid >= KH_T) return;                       // <-- the fix
    int src[EB], dst[EB];
    bool ok[EB];
#pragma unroll
    for (int i = 0; i < EB; i++) {
        int e = gid + i * KH_T;
        ok[i] = (e < TOT_E);
        if (ok[i]) {
            if (e < E_EDGES) { src[i] = ei[e]; dst[i] = ei[E_EDGES + e]; }
            else             { src[i] = dst[i] = e - E_EDGES; }
        }
    }
    int p[EB];
#pragma unroll
    for (int i = 0; i < EB; i++)
        if (ok[i]) p[i] = atomicAdd(&g_cur[dst[i]], 1);
#pragma unroll
    for (int i = 0; i < EB; i++)
        if (ok[i]) g_csr[p[i]] = src[i];
}

// ============================================================================
// KG1: layer-1 gather (fp16 feats). One warp/node; 4-wide unrolled edge loop.
// ============================================================================
__global__ void kG1(const float* __restrict__ b1) {
    int n = (blockIdx.x * blockDim.x + threadIdx.x) >> 5;
    if (n >= N_NODES) return;
    int lane = threadIdx.x & 31;
    int head = lane >> 3;
    int f = lane * 4;

    float adv = g_ad1[n * HEADS + head];
    int beg = g_off[n], cnt = g_cnt[n];

    float a0 = 0.f, a1 = 0.f, a2 = 0.f, a3 = 0.f, den = 0.f;
    int j = 0;
    for (; j + 3 < cnt; j += 4) {
        int s0 = g_csr[beg + j + 0];
        int s1 = g_csr[beg + j + 1];
        int s2 = g_csr[beg + j + 2];
        int s3 = g_csr[beg + j + 3];
        float e0 = g_as1[s0 * HEADS + head];
        float e1 = g_as1[s1 * HEADS + head];
        float e2 = g_as1[s2 * HEADS + head];
        float e3 = g_as1[s3 * HEADS + head];
        uint2 r0 = *reinterpret_cast<const uint2*>(&g_h1h[s0 * F1 + f]);
        uint2 r1 = *reinterpret_cast<const uint2*>(&g_h1h[s1 * F1 + f]);
        uint2 r2 = *reinterpret_cast<const uint2*>(&g_h1h[s2 * F1 + f]);
        uint2 r3 = *reinterpret_cast<const uint2*>(&g_h1h[s3 * F1 + f]);
        float w0 = __expf(lrelu(e0 + adv));
        float w1 = __expf(lrelu(e1 + adv));
        float w2 = __expf(lrelu(e2 + adv));
        float w3 = __expf(lrelu(e3 + adv));
        float2 pa, pb;
        pa = __half22float2(*reinterpret_cast<__half2*>(&r0.x));
        pb = __half22float2(*reinterpret_cast<__half2*>(&r0.y));
        a0 = fmaf(w0, pa.x, a0); a1 = fmaf(w0, pa.y, a1);
        a2 = fmaf(w0, pb.x, a2); a3 = fmaf(w0, pb.y, a3);
        pa = __half22float2(*reinterpret_cast<__half2*>(&r1.x));
        pb = __half22float2(*reinterpret_cast<__half2*>(&r1.y));
        a0 = fmaf(w1, pa.x, a0); a1 = fmaf(w1, pa.y, a1);
        a2 = fmaf(w1, pb.x, a2); a3 = fmaf(w1, pb.y, a3);
        pa = __half22float2(*reinterpret_cast<__half2*>(&r2.x));
        pb = __half22float2(*reinterpret_cast<__half2*>(&r2.y));
        a0 = fmaf(w2, pa.x, a0); a1 = fmaf(w2, pa.y, a1);
        a2 = fmaf(w2, pb.x, a2); a3 = fmaf(w2, pb.y, a3);
        pa = __half22float2(*reinterpret_cast<__half2*>(&r3.x));
        pb = __half22float2(*reinterpret_cast<__half2*>(&r3.y));
        a0 = fmaf(w3, pa.x, a0); a1 = fmaf(w3, pa.y, a1);
        a2 = fmaf(w3, pb.x, a2); a3 = fmaf(w3, pb.y, a3);
        den += (w0 + w1) + (w2 + w3);
    }
    for (; j < cnt; j++) {
        int s0 = g_csr[beg + j];
        float e0 = g_as1[s0 * HEADS + head];
        uint2 r0 = *reinterpret_cast<const uint2*>(&g_h1h[s0 * F1 + f]);
        float w0 = __expf(lrelu(e0 + adv));
        float2 pa = __half22float2(*reinterpret_cast<__half2*>(&r0.x));
        float2 pb = __half22float2(*reinterpret_cast<__half2*>(&r0.y));
        a0 = fmaf(w0, pa.x, a0); a1 = fmaf(w0, pa.y, a1);
        a2 = fmaf(w0, pb.x, a2); a3 = fmaf(w0, pb.y, a3);
        den += w0;
    }
    float inv = 1.f / den;
    float4 bv = *reinterpret_cast<const float4*>(&b1[f]);
    float4 o;
    o.x = elu(fmaf(a0, inv, bv.x));
    o.y = elu(fmaf(a1, inv, bv.y));
    o.z = elu(fmaf(a2, inv, bv.z));
    o.w = elu(fmaf(a3, inv, bv.w));
    *reinterpret_cast<float4*>(&g_out1[n * F1 + f]) = o;
}

// ============================================================================
// K3: h2 = out1 @ W2, register-blocked 4 nodes/warp (sW2 reads amortized 4x)
// ============================================================================
__global__ void k3_node2(const float* __restrict__ W2,
                         const float* __restrict__ as2, const float* __restrict__ ad2) {
    __shared__ float sW2[F1 * HID];       // 16 KB
    __shared__ float sH[8][4][F1];        // 16 KB
    int t = threadIdx.x;
    for (int i = t; i < F1 * HID; i += 256) sW2[i] = W2[i];
    __syncthreads();

    int wid = t >> 5, lane = t & 31;
    int n0 = blockIdx.x * 32 + wid * 4;

#pragma unroll
    for (int j = 0; j < 4; j++) {
        int n = n0 + j;
        if (n < N_NODES) {
#pragma unroll
            for (int q = 0; q < 4; q++)
                sH[wid][j][q * 32 + lane] = g_out1[n * F1 + q * 32 + lane];
        }
    }
    __syncwarp();

    float acc0 = 0.f, acc1 = 0.f, acc2 = 0.f, acc3 = 0.f;
#pragma unroll 4
    for (int k = 0; k < F1; k++) {
        float w = sW2[k * HID + lane];
        acc0 = fmaf(sH[wid][0][k], w, acc0);
        acc1 = fmaf(sH[wid][1][k], w, acc1);
        acc2 = fmaf(sH[wid][2][k], w, acc2);
        acc3 = fmaf(sH[wid][3][k], w, acc3);
    }

    float accs[4] = {acc0, acc1, acc2, acc3};
#pragma unroll
    for (int j = 0; j < 4; j++) {
        int n = n0 + j;
        float acc = accs[j];
        float ps = warp_sum_f(acc * as2[lane]);
        float pd = warp_sum_f(acc * ad2[lane]);
        if (n < N_NODES) {
            g_h2[n * HID + lane] = acc;
            if (lane == 0) { g_as2[n] = ps; g_ad2[n] = pd; }
        }
    }
}

// ============================================================================
// KG2: layer-2 gather (fp32 feats) + fused MLP head. One warp/node; 4-wide.
// ============================================================================
__global__ void kG2(const float* __restrict__ b2,  const float* __restrict__ Wc1,
                    const float* __restrict__ bc1, const float* __restrict__ Wc2,
                    const float* __restrict__ bc2, float* __restrict__ out) {
    __shared__ float sv[8][HID];
    int n = (blockIdx.x * blockDim.x + threadIdx.x) >> 5;
    if (n >= N_NODES) return;
    int lane = threadIdx.x & 31;
    int wid = (threadIdx.x >> 5) & 7;

    float adv = g_ad2[n];
    int beg = g_off[n], cnt = g_cnt[n];

    float acc = 0.f, den = 0.f;
    int j = 0;
    for (; j + 3 < cnt; j += 4) {
        int s0 = g_csr[beg + j + 0];
        int s1 = g_csr[beg + j + 1];
        int s2 = g_csr[beg + j + 2];
        int s3 = g_csr[beg + j + 3];
        float e0 = g_as2[s0];
        float e1 = g_as2[s1];
        float e2 = g_as2[s2];
        float e3 = g_as2[s3];
        float h0 = g_h2[s0 * HID + lane];
        float h1 = g_h2[s1 * HID + lane];
        float h2v = g_h2[s2 * HID + lane];
        float h3 = g_h2[s3 * HID + lane];
        float w0 = __expf(lrelu(e0 + adv));
        float w1 = __expf(lrelu(e1 + adv));
        float w2 = __expf(lrelu(e2 + adv));
        float w3 = __expf(lrelu(e3 + adv));
        acc = fmaf(w0, h0, acc);
        acc = fmaf(w1, h1, acc);
        acc = fmaf(w2, h2v, acc);
        acc = fmaf(w3, h3, acc);
        den += (w0 + w1) + (w2 + w3);
    }
    for (; j < cnt; j++) {
        int s0 = g_csr[beg + j];
        float w0 = __expf(lrelu(g_as2[s0] + adv));
        acc = fmaf(w0, g_h2[s0 * HID + lane], acc);
        den += w0;
    }
    float v = elu(acc / den + b2[lane]);
    sv[wid][lane] = v;
    __syncwarp();

    float tj = 0.f;
    if (lane < 16) {
        tj = bc1[lane];
#pragma unroll
        for (int c = 0; c < HID; c++) tj = fmaf(sv[wid][c], Wc1[c * 16 + lane], tj);
        tj = fmaxf(tj, 0.f) * Wc2[lane];
    }
#pragma unroll
    for (int o = 16; o; o >>= 1) tj += __shfl_xor_sync(0xffffffffu, tj, o);
    if (lane == 0) out[n] = tj + bc2[0];
}

// ============================================================================
extern "C" void kernel_launch(void* const* d_in, const int* in_sizes, int n_in,
                              void* d_out, int out_size) {
    const float* x   = (const float*)d_in[0];
    const int*   ei  = (const int*)  d_in[1];
    const float* W1  = (const float*)d_in[2];
    const float* as1 = (const float*)d_in[3];
    const float* ad1 = (const float*)d_in[4];
    const float* b1  = (const float*)d_in[5];
    const float* W2  = (const float*)d_in[6];
    const float* as2 = (const float*)d_in[7];
    const float* ad2 = (const float*)d_in[8];
    const float* b2  = (const float*)d_in[9];
    const float* Wc1 = (const float*)d_in[10];
    const float* bc1 = (const float*)d_in[11];
    const float* Wc2 = (const float*)d_in[12];
    const float* bc2 = (const float*)d_in[13];
    float* out = (float*)d_out;

    k1_node1<<<(N_NODES + 31) / 32, 128>>>(x, W1, as1, ad1);
    kH <<<(KH_T + 255) / 256, 256>>>(ei);
    kS1<<<NB_SCAN, SCAN_CHUNK>>>();
    kS3<<<NB_SCAN, SCAN_CHUNK>>>();
    kC <<<(KH_T + 255) / 256, 256>>>(ei);
    kG1<<<(N_NODES * 32 + 255) / 256, 256>>>(b1);
    k3_node2<<<(N_NODES + 31) / 32, 256>>>(W2, as2, ad2);
    kG2<<<(N_NODES * 32 + 255) / 256, 256>>>(b2, Wc1, bc1, Wc2, bc2, out);
}

// round 11
// speedup vs baseline: 1.6998x; 1.0044x over previous
#include <cuda_runtime.h>
#include <cuda_fp16.h>

#define N_NODES 50000
#define E_EDGES 800000
#define TOT_E   (E_EDGES + N_NODES)   // 850000, incl. self-loops
#define HID     32
#define HEADS   4
#define F1      (HEADS * HID)          // 128
#define NEG_SLOPE 0.2f

#define SCAN_CHUNK 512
#define NB_SCAN    ((N_NODES + SCAN_CHUNK - 1) / SCAN_CHUNK)   // 98

// ---- scratch (device globals; no allocation allowed) ----
__device__ int   g_cnt[N_NODES];
__device__ int   g_off[N_NODES];
__device__ int   g_cur[N_NODES];
__device__ int   g_total;                 // global cursor for kOff
__device__ int   g_csr[TOT_E];
__device__ __align__(16) __half g_h1h[N_NODES * F1];   // layer1 feats fp16
__device__ __align__(16) float  g_as1[N_NODES * HEADS];
__device__ __align__(16) float  g_ad1[N_NODES * HEADS];
__device__ __align__(16) float  g_out1[N_NODES * F1];  // post-softmax, post-ELU
__device__ __align__(16) float  g_h2[N_NODES * HID];   // layer2 feats fp32
__device__ float g_as2[N_NODES];
__device__ float g_ad2[N_NODES];

__device__ __forceinline__ float warp_sum_f(float v) {
#pragma unroll
    for (int o = 16; o; o >>= 1) v += __shfl_xor_sync(0xffffffffu, v, o);
    return v;
}
__device__ __forceinline__ float lrelu(float e) { return e > 0.f ? e : NEG_SLOPE * e; }
__device__ __forceinline__ float elu(float v)   { return v > 0.f ? v : __expf(v) - 1.f; }

// ============================================================================
// K1: h1 = x @ W1 (fp16); attention scalars via a = x·(W1@attᵀ).
// Also zeros g_cnt and g_total. 128 threads, 32 nodes per block.
// ============================================================================
__global__ void k1_node1(const float* __restrict__ x,  const float* __restrict__ W1,
                         const float* __restrict__ as1, const float* __restrict__ ad1) {
    __shared__ float sW[5 * F1];
    __shared__ float sva[5 * HEADS], svb[5 * HEADS];
    int t = threadIdx.x;
    int n0 = blockIdx.x * 32;
    if (t < 32 && n0 + t < N_NODES) g_cnt[n0 + t] = 0;
    if (blockIdx.x == 0 && t == 32) g_total = 0;

    for (int i = t; i < 5 * F1; i += 128) sW[i] = W1[i];
    if (t < 5 * HEADS) {
        int k = t / HEADS, h = t % HEADS;
        float s = 0.f, d = 0.f;
        for (int c = 0; c < HID; c++) {
            float w = W1[k * F1 + h * HID + c];
            s = fmaf(w, as1[h * HID + c], s);
            d = fmaf(w, ad1[h * HID + c], d);
        }
        sva[t] = s; svb[t] = d;
    }
    __syncthreads();

    for (int j = 0; j < 32; j++) {
        int n = n0 + j;
        if (n >= N_NODES) return;
        float xv[5];
#pragma unroll
        for (int k = 0; k < 5; k++) xv[k] = x[n * 5 + k];
        float h = 0.f;
#pragma unroll
        for (int k = 0; k < 5; k++) h = fmaf(xv[k], sW[k * F1 + t], h);
        g_h1h[n * F1 + t] = __float2half_rn(h);
        if (t < HEADS) {
            float s = 0.f, d = 0.f;
#pragma unroll
            for (int k = 0; k < 5; k++) {
                s = fmaf(xv[k], sva[k * HEADS + t], s);
                d = fmaf(xv[k], svb[k * HEADS + t], d);
            }
            g_as1[n * HEADS + t] = s;
            g_ad1[n * HEADS + t] = d;
        }
    }
}

// ============================================================================
// kH: histogram by dst — 4 striped edges/thread, stripe guard enforced
// ============================================================================
#define EB 4
#define KH_T ((TOT_E + EB - 1) / EB)   // 212500 stripe width
__global__ void kH(const int* __restrict__ ei) {
    int gid = blockIdx.x * blockDim.x + threadIdx.x;
    if (gid >= KH_T) return;
#pragma unroll
    for (int i = 0; i < EB; i++) {
        int e = gid + i * KH_T;
        if (e < TOT_E) {
            int dst = (e < E_EDGES) ? ei[E_EDGES + e] : (e - E_EDGES);
            atomicAdd(&g_cnt[dst], 1);
        }
    }
}

// ============================================================================
// kOff: single-kernel offset assignment. Each block scans its 512 counts,
// claims a contiguous base via ONE atomicAdd on g_total, writes offsets.
// Row order across blocks is arbitrary — rows stay contiguous, which is all
// the gathers need (CSR ordering was already non-deterministic via kC).
// ============================================================================
__global__ void kOff() {
    __shared__ int ws[SCAN_CHUNK / 32 + 1];
    __shared__ int sbase;
    int t = threadIdx.x, b = blockIdx.x;
    int i = b * SCAN_CHUNK + t;
    int lane = t & 31, wid = t >> 5;

    int v = (i < N_NODES) ? g_cnt[i] : 0;
    int x = v;
#pragma unroll
    for (int o = 1; o < 32; o <<= 1) {              // inclusive warp scan (all lanes)
        int y = __shfl_up_sync(0xffffffffu, x, o);
        if (lane >= o) x += y;
    }
    if (lane == 31) ws[wid + 1] = x;
    __syncthreads();
    if (t == 0) {
        ws[0] = 0;
        for (int w = 1; w <= SCAN_CHUNK / 32; w++) ws[w] += ws[w - 1];
        sbase = atomicAdd(&g_total, ws[SCAN_CHUNK / 32]);   // claim block base
    }
    __syncthreads();
    int excl = x - v + ws[wid] + sbase;
    if (i < N_NODES) { g_off[i] = excl; g_cur[i] = excl; }
}

// ============================================================================
// kC: scatter src by dst — 4 striped edges/thread, stripe guard enforced
// ============================================================================
__global__ void kC(const int* __restrict__ ei) {
    int gid = blockIdx.x * blockDim.x + threadIdx.x;
    if (gid >= KH_T) return;
    int src[EB], dst[EB];
    bool ok[EB];
#pragma unroll
    for (int i = 0; i < EB; i++) {
        int e = gid + i * KH_T;
        ok[i] = (e < TOT_E);
        if (ok[i]) {
            if (e < E_EDGES) { src[i] = ei[e]; dst[i] = ei[E_EDGES + e]; }
            else             { src[i] = dst[i] = e - E_EDGES; }
        }
    }
    int p[EB];
#pragma unroll
    for (int i = 0; i < EB; i++)
        if (ok[i]) p[i] = atomicAdd(&g_cur[dst[i]], 1);
#pragma unroll
    for (int i = 0; i < EB; i++)
        if (ok[i]) g_csr[p[i]] = src[i];
}

// ============================================================================
// KG1: layer-1 gather (fp16 feats). One warp/node; 8-wide unrolled edge loop
// (8 independent csr->(as1,h1) chains in flight; gathers are latency-bound).
// ============================================================================
__global__ void kG1(const float* __restrict__ b1) {
    int n = (blockIdx.x * blockDim.x + threadIdx.x) >> 5;
    if (n >= N_NODES) return;
    int lane = threadIdx.x & 31;
    int head = lane >> 3;
    int f = lane * 4;

    float adv = g_ad1[n * HEADS + head];
    int beg = g_off[n], cnt = g_cnt[n];

    float a0 = 0.f, a1 = 0.f, a2 = 0.f, a3 = 0.f, den = 0.f;
    int j = 0;
    for (; j + 7 < cnt; j += 8) {
        int s[8];
#pragma unroll
        for (int q = 0; q < 8; q++) s[q] = g_csr[beg + j + q];
        float e[8];
#pragma unroll
        for (int q = 0; q < 8; q++) e[q] = g_as1[s[q] * HEADS + head];
        uint2 r[8];
#pragma unroll
        for (int q = 0; q < 8; q++)
            r[q] = *reinterpret_cast<const uint2*>(&g_h1h[s[q] * F1 + f]);
#pragma unroll
        for (int q = 0; q < 8; q++) {
            float w = __expf(lrelu(e[q] + adv));
            float2 pa = __half22float2(*reinterpret_cast<__half2*>(&r[q].x));
            float2 pb = __half22float2(*reinterpret_cast<__half2*>(&r[q].y));
            a0 = fmaf(w, pa.x, a0); a1 = fmaf(w, pa.y, a1);
            a2 = fmaf(w, pb.x, a2); a3 = fmaf(w, pb.y, a3);
            den += w;
        }
    }
    for (; j < cnt; j++) {
        int s0 = g_csr[beg + j];
        float e0 = g_as1[s0 * HEADS + head];
        uint2 r0 = *reinterpret_cast<const uint2*>(&g_h1h[s0 * F1 + f]);
        float w0 = __expf(lrelu(e0 + adv));
        float2 pa = __half22float2(*reinterpret_cast<__half2*>(&r0.x));
        float2 pb = __half22float2(*reinterpret_cast<__half2*>(&r0.y));
        a0 = fmaf(w0, pa.x, a0); a1 = fmaf(w0, pa.y, a1);
        a2 = fmaf(w0, pb.x, a2); a3 = fmaf(w0, pb.y, a3);
        den += w0;
    }
    float inv = 1.f / den;
    float4 bv = *reinterpret_cast<const float4*>(&b1[f]);
    float4 o;
    o.x = elu(fmaf(a0, inv, bv.x));
    o.y = elu(fmaf(a1, inv, bv.y));
    o.z = elu(fmaf(a2, inv, bv.z));
    o.w = elu(fmaf(a3, inv, bv.w));
    *reinterpret_cast<float4*>(&g_out1[n * F1 + f]) = o;
}

// ============================================================================
// K3: h2 = out1 @ W2, register-blocked 4 nodes/warp (sW2 reads amortized 4x)
// ============================================================================
__global__ void k3_node2(const float* __restrict__ W2,
                         const float* __restrict__ as2, const float* __restrict__ ad2) {
    __shared__ float sW2[F1 * HID];       // 16 KB
    __shared__ float sH[8][4][F1];        // 16 KB
    int t = threadIdx.x;
    for (int i = t; i < F1 * HID; i += 256) sW2[i] = W2[i];
    __syncthreads();

    int wid = t >> 5, lane = t & 31;
    int n0 = blockIdx.x * 32 + wid * 4;

#pragma unroll
    for (int j = 0; j < 4; j++) {
        int n = n0 + j;
        if (n < N_NODES) {
#pragma unroll
            for (int q = 0; q < 4; q++)
                sH[wid][j][q * 32 + lane] = g_out1[n * F1 + q * 32 + lane];
        }
    }
    __syncwarp();

    float acc0 = 0.f, acc1 = 0.f, acc2 = 0.f, acc3 = 0.f;
#pragma unroll 4
    for (int k = 0; k < F1; k++) {
        float w = sW2[k * HID + lane];
        acc0 = fmaf(sH[wid][0][k], w, acc0);
        acc1 = fmaf(sH[wid][1][k], w, acc1);
        acc2 = fmaf(sH[wid][2][k], w, acc2);
        acc3 = fmaf(sH[wid][3][k], w, acc3);
    }

    float accs[4] = {acc0, acc1, acc2, acc3};
#pragma unroll
    for (int j = 0; j < 4; j++) {
        int n = n0 + j;
        float acc = accs[j];
        float ps = warp_sum_f(acc * as2[lane]);
        float pd = warp_sum_f(acc * ad2[lane]);
        if (n < N_NODES) {
            g_h2[n * HID + lane] = acc;
            if (lane == 0) { g_as2[n] = ps; g_ad2[n] = pd; }
        }
    }
}

// ============================================================================
// KG2: layer-2 gather (fp32) + fused MLP head. One warp/node; 8-wide unroll.
// ============================================================================
__global__ void kG2(const float* __restrict__ b2,  const float* __restrict__ Wc1,
                    const float* __restrict__ bc1, const float* __restrict__ Wc2,
                    const float* __restrict__ bc2, float* __restrict__ out) {
    __shared__ float sv[8][HID];
    int n = (blockIdx.x * blockDim.x + threadIdx.x) >> 5;
    if (n >= N_NODES) return;
    int lane = threadIdx.x & 31;
    int wid = (threadIdx.x >> 5) & 7;

    float adv = g_ad2[n];
    int beg = g_off[n], cnt = g_cnt[n];

    float acc = 0.f, den = 0.f;
    int j = 0;
    for (; j + 7 < cnt; j += 8) {
        int s[8];
#pragma unroll
        for (int q = 0; q < 8; q++) s[q] = g_csr[beg + j + q];
        float e[8], h[8];
#pragma unroll
        for (int q = 0; q < 8; q++) e[q] = g_as2[s[q]];
#pragma unroll
        for (int q = 0; q < 8; q++) h[q] = g_h2[s[q] * HID + lane];
#pragma unroll
        for (int q = 0; q < 8; q++) {
            float w = __expf(lrelu(e[q] + adv));
            acc = fmaf(w, h[q], acc);
            den += w;
        }
    }
    for (; j < cnt; j++) {
        int s0 = g_csr[beg + j];
        float w0 = __expf(lrelu(g_as2[s0] + adv));
        acc = fmaf(w0, g_h2[s0 * HID + lane], acc);
        den += w0;
    }
    float v = elu(acc / den + b2[lane]);
    sv[wid][lane] = v;
    __syncwarp();

    float tj = 0.f;
    if (lane < 16) {
        tj = bc1[lane];
#pragma unroll
        for (int c = 0; c < HID; c++) tj = fmaf(sv[wid][c], Wc1[c * 16 + lane], tj);
        tj = fmaxf(tj, 0.f) * Wc2[lane];
    }
#pragma unroll
    for (int o = 16; o; o >>= 1) tj += __shfl_xor_sync(0xffffffffu, tj, o);
    if (lane == 0) out[n] = tj + bc2[0];
}

// ============================================================================
extern "C" void kernel_launch(void* const* d_in, const int* in_sizes, int n_in,
                              void* d_out, int out_size) {
    const float* x   = (const float*)d_in[0];
    const int*   ei  = (const int*)  d_in[1];
    const float* W1  = (const float*)d_in[2];
    const float* as1 = (const float*)d_in[3];
    const float* ad1 = (const float*)d_in[4];
    const float* b1  = (const float*)d_in[5];
    const float* W2  = (const float*)d_in[6];
    const float* as2 = (const float*)d_in[7];
    const float* ad2 = (const float*)d_in[8];
    const float* b2  = (const float*)d_in[9];
    const float* Wc1 = (const float*)d_in[10];
    const float* bc1 = (const float*)d_in[11];
    const float* Wc2 = (const float*)d_in[12];
    const float* bc2 = (const float*)d_in[13];
    float* out = (float*)d_out;

    k1_node1<<<(N_NODES + 31) / 32, 128>>>(x, W1, as1, ad1);  // zeros g_cnt, g_total
    kH  <<<(KH_T + 255) / 256, 256>>>(ei);
    kOff<<<NB_SCAN, SCAN_CHUNK>>>();                           // single-kernel offsets
    kC  <<<(KH_T + 255) / 256, 256>>>(ei);
    kG1 <<<(N_NODES * 32 + 255) / 256, 256>>>(b1);
    k3_node2<<<(N_NODES + 31) / 32, 256>>>(W2, as2, ad2);
    kG2 <<<(N_NODES * 32 + 255) / 256, 256>>>(b2, Wc1, bc1, Wc2, bc2, out);
}

// round 12
// speedup vs baseline: 1.7411x; 1.0243x over previous
#include <cuda_runtime.h>
#include <cuda_fp16.h>

#define N_NODES 50000
#define E_EDGES 800000
#define TOT_E   (E_EDGES + N_NODES)   // 850000, incl. self-loops
#define HID     32
#define HEADS   4
#define F1      (HEADS * HID)          // 128
#define NEG_SLOPE 0.2f

#define SCAN_CHUNK 512
#define NB_SCAN    ((N_NODES + SCAN_CHUNK - 1) / SCAN_CHUNK)   // 98

// ---- scratch (device globals; no allocation allowed) ----
__device__ int   g_cnt[N_NODES];
__device__ int   g_off[N_NODES];
__device__ int   g_total;                 // global cursor for kOff
__device__ int   g_rank[TOT_E];           // edge's slot within its dst row
__device__ int   g_csr[TOT_E];
__device__ __align__(16) __half g_h1h[N_NODES * F1];   // layer1 feats fp16
__device__ __align__(16) float  g_as1[N_NODES * HEADS];
__device__ __align__(16) float  g_ad1[N_NODES * HEADS];
__device__ __align__(16) float  g_out1[N_NODES * F1];  // post-softmax, post-ELU
__device__ __align__(16) float  g_h2[N_NODES * HID];   // layer2 feats fp32
__device__ float g_as2[N_NODES];
__device__ float g_ad2[N_NODES];

__device__ __forceinline__ float warp_sum_f(float v) {
#pragma unroll
    for (int o = 16; o; o >>= 1) v += __shfl_xor_sync(0xffffffffu, v, o);
    return v;
}
__device__ __forceinline__ float lrelu(float e) { return e > 0.f ? e : NEG_SLOPE * e; }
__device__ __forceinline__ float elu(float v)   { return v > 0.f ? v : __expf(v) - 1.f; }

// ============================================================================
// K1: h1 = x @ W1 (fp16); attention scalars via a = x·(W1@attᵀ).
// Also zeros g_cnt and g_total. 128 threads, 32 nodes per block.
// ============================================================================
__global__ void k1_node1(const float* __restrict__ x,  const float* __restrict__ W1,
                         const float* __restrict__ as1, const float* __restrict__ ad1) {
    __shared__ float sW[5 * F1];
    __shared__ float sva[5 * HEADS], svb[5 * HEADS];
    int t = threadIdx.x;
    int n0 = blockIdx.x * 32;
    if (t < 32 && n0 + t < N_NODES) g_cnt[n0 + t] = 0;
    if (blockIdx.x == 0 && t == 32) g_total = 0;

    for (int i = t; i < 5 * F1; i += 128) sW[i] = W1[i];
    if (t < 5 * HEADS) {
        int k = t / HEADS, h = t % HEADS;
        float s = 0.f, d = 0.f;
        for (int c = 0; c < HID; c++) {
            float w = W1[k * F1 + h * HID + c];
            s = fmaf(w, as1[h * HID + c], s);
            d = fmaf(w, ad1[h * HID + c], d);
        }
        sva[t] = s; svb[t] = d;
    }
    __syncthreads();

    for (int j = 0; j < 32; j++) {
        int n = n0 + j;
        if (n >= N_NODES) return;
        float xv[5];
#pragma unroll
        for (int k = 0; k < 5; k++) xv[k] = x[n * 5 + k];
        float h = 0.f;
#pragma unroll
        for (int k = 0; k < 5; k++) h = fmaf(xv[k], sW[k * F1 + t], h);
        g_h1h[n * F1 + t] = __float2half_rn(h);
        if (t < HEADS) {
            float s = 0.f, d = 0.f;
#pragma unroll
            for (int k = 0; k < 5; k++) {
                s = fmaf(xv[k], sva[k * HEADS + t], s);
                d = fmaf(xv[k], svb[k * HEADS + t], d);
            }
            g_as1[n * HEADS + t] = s;
            g_ad1[n * HEADS + t] = d;
        }
    }
}

// ============================================================================
// kH: histogram by dst AND record each edge's within-row rank (the atomicAdd
// return we previously discarded). The rank store is independent/coalesced,
// so the ATOMG return latency is hidden by TLP. 4 striped edges/thread.
// ============================================================================
#define EB 4
#define KH_T ((TOT_E + EB - 1) / EB)   // 212500 stripe width
__global__ void kH(const int* __restrict__ ei) {
    int gid = blockIdx.x * blockDim.x + threadIdx.x;
    if (gid >= KH_T) return;
#pragma unroll
    for (int i = 0; i < EB; i++) {
        int e = gid + i * KH_T;
        if (e < TOT_E) {
            int dst = (e < E_EDGES) ? ei[E_EDGES + e] : (e - E_EDGES);
            g_rank[e] = atomicAdd(&g_cnt[dst], 1);
        }
    }
}

// ============================================================================
// kOff: single-kernel offset assignment (block scan + one atomicAdd base claim)
// ============================================================================
__global__ void kOff() {
    __shared__ int ws[SCAN_CHUNK / 32 + 1];
    __shared__ int sbase;
    int t = threadIdx.x, b = blockIdx.x;
    int i = b * SCAN_CHUNK + t;
    int lane = t & 31, wid = t >> 5;

    int v = (i < N_NODES) ? g_cnt[i] : 0;
    int x = v;
#pragma unroll
    for (int o = 1; o < 32; o <<= 1) {              // inclusive warp scan (all lanes)
        int y = __shfl_up_sync(0xffffffffu, x, o);
        if (lane >= o) x += y;
    }
    if (lane == 31) ws[wid + 1] = x;
    __syncthreads();
    if (t == 0) {
        ws[0] = 0;
        for (int w = 1; w <= SCAN_CHUNK / 32; w++) ws[w] += ws[w - 1];
        sbase = atomicAdd(&g_total, ws[SCAN_CHUNK / 32]);   // claim block base
    }
    __syncthreads();
    int excl = x - v + ws[wid] + sbase;
    if (i < N_NODES) g_off[i] = excl;
}

// ============================================================================
// kC: ATOMIC-FREE scatter — slot is g_off[dst] + g_rank[e]. One edge/thread,
// full TLP; only plain loads (2 coalesced + 1 gather) and 1 scattered store.
// ============================================================================
__global__ void kC(const int* __restrict__ ei) {
    int e = blockIdx.x * blockDim.x + threadIdx.x;
    if (e >= TOT_E) return;
    int src, dst;
    if (e < E_EDGES) { src = ei[e]; dst = ei[E_EDGES + e]; }
    else             { src = dst = e - E_EDGES; }
    g_csr[g_off[dst] + g_rank[e]] = src;
}

// ============================================================================
// KG1: layer-1 gather (fp16 feats). One warp/node; 4-wide (8-wide measured
// slower in R11 — MLP saturates at 4).
// ============================================================================
__global__ void kG1(const float* __restrict__ b1) {
    int n = (blockIdx.x * blockDim.x + threadIdx.x) >> 5;
    if (n >= N_NODES) return;
    int lane = threadIdx.x & 31;
    int head = lane >> 3;
    int f = lane * 4;

    float adv = g_ad1[n * HEADS + head];
    int beg = g_off[n], cnt = g_cnt[n];

    float a0 = 0.f, a1 = 0.f, a2 = 0.f, a3 = 0.f, den = 0.f;
    int j = 0;
    for (; j + 3 < cnt; j += 4) {
        int s0 = g_csr[beg + j + 0];
        int s1 = g_csr[beg + j + 1];
        int s2 = g_csr[beg + j + 2];
        int s3 = g_csr[beg + j + 3];
        float e0 = g_as1[s0 * HEADS + head];
        float e1 = g_as1[s1 * HEADS + head];
        float e2 = g_as1[s2 * HEADS + head];
        float e3 = g_as1[s3 * HEADS + head];
        uint2 r0 = *reinterpret_cast<const uint2*>(&g_h1h[s0 * F1 + f]);
        uint2 r1 = *reinterpret_cast<const uint2*>(&g_h1h[s1 * F1 + f]);
        uint2 r2 = *reinterpret_cast<const uint2*>(&g_h1h[s2 * F1 + f]);
        uint2 r3 = *reinterpret_cast<const uint2*>(&g_h1h[s3 * F1 + f]);
        float w0 = __expf(lrelu(e0 + adv));
        float w1 = __expf(lrelu(e1 + adv));
        float w2 = __expf(lrelu(e2 + adv));
        float w3 = __expf(lrelu(e3 + adv));
        float2 pa, pb;
        pa = __half22float2(*reinterpret_cast<__half2*>(&r0.x));
        pb = __half22float2(*reinterpret_cast<__half2*>(&r0.y));
        a0 = fmaf(w0, pa.x, a0); a1 = fmaf(w0, pa.y, a1);
        a2 = fmaf(w0, pb.x, a2); a3 = fmaf(w0, pb.y, a3);
        pa = __half22float2(*reinterpret_cast<__half2*>(&r1.x));
        pb = __half22float2(*reinterpret_cast<__half2*>(&r1.y));
        a0 = fmaf(w1, pa.x, a0); a1 = fmaf(w1, pa.y, a1);
        a2 = fmaf(w1, pb.x, a2); a3 = fmaf(w1, pb.y, a3);
        pa = __half22float2(*reinterpret_cast<__half2*>(&r2.x));
        pb = __half22float2(*reinterpret_cast<__half2*>(&r2.y));
        a0 = fmaf(w2, pa.x, a0); a1 = fmaf(w2, pa.y, a1);
        a2 = fmaf(w2, pb.x, a2); a3 = fmaf(w2, pb.y, a3);
        pa = __half22float2(*reinterpret_cast<__half2*>(&r3.x));
        pb = __half22float2(*reinterpret_cast<__half2*>(&r3.y));
        a0 = fmaf(w3, pa.x, a0); a1 = fmaf(w3, pa.y, a1);
        a2 = fmaf(w3, pb.x, a2); a3 = fmaf(w3, pb.y, a3);
        den += (w0 + w1) + (w2 + w3);
    }
    for (; j < cnt; j++) {
        int s0 = g_csr[beg + j];
        float e0 = g_as1[s0 * HEADS + head];
        uint2 r0 = *reinterpret_cast<const uint2*>(&g_h1h[s0 * F1 + f]);
        float w0 = __expf(lrelu(e0 + adv));
        float2 pa = __half22float2(*reinterpret_cast<__half2*>(&r0.x));
        float2 pb = __half22float2(*reinterpret_cast<__half2*>(&r0.y));
        a0 = fmaf(w0, pa.x, a0); a1 = fmaf(w0, pa.y, a1);
        a2 = fmaf(w0, pb.x, a2); a3 = fmaf(w0, pb.y, a3);
        den += w0;
    }
    float inv = 1.f / den;
    float4 bv = *reinterpret_cast<const float4*>(&b1[f]);
    float4 o;
    o.x = elu(fmaf(a0, inv, bv.x));
    o.y = elu(fmaf(a1, inv, bv.y));
    o.z = elu(fmaf(a2, inv, bv.z));
    o.w = elu(fmaf(a3, inv, bv.w));
    *reinterpret_cast<float4*>(&g_out1[n * F1 + f]) = o;
}

// ============================================================================
// K3: h2 = out1 @ W2, register-blocked 4 nodes/warp
// ============================================================================
__global__ void k3_node2(const float* __restrict__ W2,
                         const float* __restrict__ as2, const float* __restrict__ ad2) {
    __shared__ float sW2[F1 * HID];       // 16 KB
    __shared__ float sH[8][4][F1];        // 16 KB
    int t = threadIdx.x;
    for (int i = t; i < F1 * HID; i += 256) sW2[i] = W2[i];
    __syncthreads();

    int wid = t >> 5, lane = t & 31;
    int n0 = blockIdx.x * 32 + wid * 4;

#pragma unroll
    for (int j = 0; j < 4; j++) {
        int n = n0 + j;
        if (n < N_NODES) {
#pragma unroll
            for (int q = 0; q < 4; q++)
                sH[wid][j][q * 32 + lane] = g_out1[n * F1 + q * 32 + lane];
        }
    }
    __syncwarp();

    float acc0 = 0.f, acc1 = 0.f, acc2 = 0.f, acc3 = 0.f;
#pragma unroll 4
    for (int k = 0; k < F1; k++) {
        float w = sW2[k * HID + lane];
        acc0 = fmaf(sH[wid][0][k], w, acc0);
        acc1 = fmaf(sH[wid][1][k], w, acc1);
        acc2 = fmaf(sH[wid][2][k], w, acc2);
        acc3 = fmaf(sH[wid][3][k], w, acc3);
    }

    float accs[4] = {acc0, acc1, acc2, acc3};
#pragma unroll
    for (int j = 0; j < 4; j++) {
        int n = n0 + j;
        float acc = accs[j];
        float ps = warp_sum_f(acc * as2[lane]);
        float pd = warp_sum_f(acc * ad2[lane]);
        if (n < N_NODES) {
            g_h2[n * HID + lane] = acc;
            if (lane == 0) { g_as2[n] = ps; g_ad2[n] = pd; }
        }
    }
}

// ============================================================================
// KG2: layer-2 gather (fp32) + fused MLP head. One warp/node; 4-wide.
// ============================================================================
__global__ void kG2(const float* __restrict__ b2,  const float* __restrict__ Wc1,
                    const float* __restrict__ bc1, const float* __restrict__ Wc2,
                    const float* __restrict__ bc2, float* __restrict__ out) {
    __shared__ float sv[8][HID];
    int n = (blockIdx.x * blockDim.x + threadIdx.x) >> 5;
    if (n >= N_NODES) return;
    int lane = threadIdx.x & 31;
    int wid = (threadIdx.x >> 5) & 7;

    float adv = g_ad2[n];
    int beg = g_off[n], cnt = g_cnt[n];

    float acc = 0.f, den = 0.f;
    int j = 0;
    for (; j + 3 < cnt; j += 4) {
        int s0 = g_csr[beg + j + 0];
        int s1 = g_csr[beg + j + 1];
        int s2 = g_csr[beg + j + 2];
        int s3 = g_csr[beg + j + 3];
        float e0 = g_as2[s0];
        float e1 = g_as2[s1];
        float e2 = g_as2[s2];
        float e3 = g_as2[s3];
        float h0 = g_h2[s0 * HID + lane];
        float h1 = g_h2[s1 * HID + lane];
        float h2v = g_h2[s2 * HID + lane];
        float h3 = g_h2[s3 * HID + lane];
        float w0 = __expf(lrelu(e0 + adv));
        float w1 = __expf(lrelu(e1 + adv));
        float w2 = __expf(lrelu(e2 + adv));
        float w3 = __expf(lrelu(e3 + adv));
        acc = fmaf(w0, h0, acc);
        acc = fmaf(w1, h1, acc);
        acc = fmaf(w2, h2v, acc);
        acc = fmaf(w3, h3, acc);
        den += (w0 + w1) + (w2 + w3);
    }
    for (; j < cnt; j++) {
        int s0 = g_csr[beg + j];
        float w0 = __expf(lrelu(g_as2[s0] + adv));
        acc = fmaf(w0, g_h2[s0 * HID + lane], acc);
        den += w0;
    }
    float v = elu(acc / den + b2[lane]);
    sv[wid][lane] = v;
    __syncwarp();

    float tj = 0.f;
    if (lane < 16) {
        tj = bc1[lane];
#pragma unroll
        for (int c = 0; c < HID; c++) tj = fmaf(sv[wid][c], Wc1[c * 16 + lane], tj);
        tj = fmaxf(tj, 0.f) * Wc2[lane];
    }
#pragma unroll
    for (int o = 16; o; o >>= 1) tj += __shfl_xor_sync(0xffffffffu, tj, o);
    if (lane == 0) out[n] = tj + bc2[0];
}

// ============================================================================
extern "C" void kernel_launch(void* const* d_in, const int* in_sizes, int n_in,
                              void* d_out, int out_size) {
    const float* x   = (const float*)d_in[0];
    const int*   ei  = (const int*)  d_in[1];
    const float* W1  = (const float*)d_in[2];
    const float* as1 = (const float*)d_in[3];
    const float* ad1 = (const float*)d_in[4];
    const float* b1  = (const float*)d_in[5];
    const float* W2  = (const float*)d_in[6];
    const float* as2 = (const float*)d_in[7];
    const float* ad2 = (const float*)d_in[8];
    const float* b2  = (const float*)d_in[9];
    const float* Wc1 = (const float*)d_in[10];
    const float* bc1 = (const float*)d_in[11];
    const float* Wc2 = (const float*)d_in[12];
    const float* bc2 = (const float*)d_in[13];
    float* out = (float*)d_out;

    k1_node1<<<(N_NODES + 31) / 32, 128>>>(x, W1, as1, ad1);  // zeros g_cnt, g_total
    kH  <<<(KH_T + 255) / 256, 256>>>(ei);                     // counts + ranks
    kOff<<<NB_SCAN, SCAN_CHUNK>>>();
    kC  <<<(TOT_E + 255) / 256, 256>>>(ei);                    // atomic-free scatter
    kG1 <<<(N_NODES * 32 + 255) / 256, 256>>>(b1);
    k3_node2<<<(N_NODES + 31) / 32, 256>>>(W2, as2, ad2);
    kG2 <<<(N_NODES * 32 + 255) / 256, 256>>>(b2, Wc1, bc1, Wc2, bc2, out);
}